// round 2
// baseline (speedup 1.0000x reference)
#include <cuda_runtime.h>
#include <cuda_fp16.h>
#include <math.h>
#include <stdint.h>

// Problem dims
#define BB 64
#define TT 256
#define IIN 1024
#define HHID 512
// M = BB*TT = 16384

// ---------------- device scratch (static: no allocations allowed) ----------------
__device__ __half d_xh[16384u * 1024u];          // x in fp16
__device__ __half d_wih1[1536u * 1024u];
__device__ __half d_whh1[1536u * 512u];
__device__ __half d_wih2[3072u * 512u];
__device__ __half d_whh2[3072u * 1024u];
__device__ float  d_gx1[16384u * 1536u];         // x @ W_ih1^T + b_ih1
__device__ float  d_gx2[16384u * 3072u];         // relu(h1) @ W_ih2^T + b_ih2
__device__ __half d_h1seq[16384u * 512u];        // relu(h1) sequence, fp16
__device__ __half d_hbuf16[2][64 * 1024];        // double-buffered hidden (fp16 for MMA)
__device__ float  d_hbuf32[2][64 * 1024];        // fp32 master hidden
__device__ unsigned int d_bar1;
__device__ unsigned int d_bar2;

// ---------------- helpers ----------------
__device__ __forceinline__ uint32_t ld32h(const __half* p) {
    return *reinterpret_cast<const uint32_t*>(p);
}

__device__ __forceinline__ void mma16816(float* c, const uint32_t* a, const uint32_t* b) {
    asm volatile(
        "mma.sync.aligned.m16n8k16.row.col.f32.f16.f16.f32 "
        "{%0,%1,%2,%3}, {%4,%5,%6,%7}, {%8,%9}, {%0,%1,%2,%3};\n"
        : "+f"(c[0]), "+f"(c[1]), "+f"(c[2]), "+f"(c[3])
        : "r"(a[0]), "r"(a[1]), "r"(a[2]), "r"(a[3]), "r"(b[0]), "r"(b[1]));
}

__device__ __forceinline__ float sigmoidf_(float x) {
    return 1.0f / (1.0f + __expf(-x));
}

// Grid-wide barrier via monotonically-increasing counter (reset each launch by prep).
__device__ __forceinline__ void gridbar(unsigned int* ctr, unsigned int target) {
    __syncthreads();
    if (threadIdx.x == 0) {
        __threadfence();
        unsigned int arrived = atomicAdd(ctr, 1u) + 1u;
        if (arrived < target) {
            while (*reinterpret_cast<volatile unsigned int*>(ctr) < target) {
                __nanosleep(64);
            }
        }
        __threadfence();
    }
    __syncthreads();
}

// ---------------- prep: fp32 -> fp16 conversions + barrier reset ----------------
__global__ void prep_kernel(const float* __restrict__ x,
                            const float* __restrict__ wih1, const float* __restrict__ whh1,
                            const float* __restrict__ wih2, const float* __restrict__ whh2) {
    long idx = (long)blockIdx.x * blockDim.x + threadIdx.x;
    long stride = (long)gridDim.x * blockDim.x;
    if (idx == 0) { d_bar1 = 0u; d_bar2 = 0u; }
    for (long i = idx; i < 16384L * 1024L; i += stride) d_xh[i]   = __float2half(x[i]);
    for (long i = idx; i < 1536L * 1024L;  i += stride) d_wih1[i] = __float2half(wih1[i]);
    for (long i = idx; i < 1536L * 512L;   i += stride) d_whh1[i] = __float2half(whh1[i]);
    for (long i = idx; i < 3072L * 512L;   i += stride) d_wih2[i] = __float2half(wih2[i]);
    for (long i = idx; i < 3072L * 1024L;  i += stride) d_whh2[i] = __float2half(whh2[i]);
}

// ---------------- big GEMM: C[M,N] = A[M,K] @ W[N,K]^T + bias ----------------
// CTA tile 64(M) x 256(N); 8 warps as 2x4, warp tile 32x64. Direct-global fragment loads.
__global__ void gemm_tn_kernel(const __half* __restrict__ A, const __half* __restrict__ W,
                               const float* __restrict__ bias, float* __restrict__ C,
                               int M, int N, int K) {
    const int bn = blockIdx.x * 256;
    const int bm = blockIdx.y * 64;
    const int w = threadIdx.x >> 5, lane = threadIdx.x & 31;
    const int g = lane >> 2, tg = lane & 3;
    const int wm = (w >> 2) * 32;   // 0 or 32
    const int wn = (w & 3) * 64;    // 0,64,128,192

    float acc[2][8][4];
#pragma unroll
    for (int mt = 0; mt < 2; mt++)
#pragma unroll
        for (int nt = 0; nt < 8; nt++)
#pragma unroll
            for (int e = 0; e < 4; e++) acc[mt][nt][e] = 0.0f;

    for (int k0 = 0; k0 < K; k0 += 16) {
        uint32_t a[2][4];
#pragma unroll
        for (int mt = 0; mt < 2; mt++) {
            int r0 = bm + wm + mt * 16 + g;
            int r1 = r0 + 8;
            const __half* pa = A + (long)r0 * K + k0 + tg * 2;
            const __half* pb = A + (long)r1 * K + k0 + tg * 2;
            a[mt][0] = ld32h(pa);
            a[mt][1] = ld32h(pb);
            a[mt][2] = ld32h(pa + 8);
            a[mt][3] = ld32h(pb + 8);
        }
        uint32_t bf[8][2];
#pragma unroll
        for (int nt = 0; nt < 8; nt++) {
            int n = bn + wn + nt * 8 + g;
            const __half* pw = W + (long)n * K + k0 + tg * 2;
            bf[nt][0] = ld32h(pw);
            bf[nt][1] = ld32h(pw + 8);
        }
#pragma unroll
        for (int mt = 0; mt < 2; mt++)
#pragma unroll
            for (int nt = 0; nt < 8; nt++) mma16816(acc[mt][nt], a[mt], bf[nt]);
    }

#pragma unroll
    for (int mt = 0; mt < 2; mt++) {
        int row0 = bm + wm + mt * 16 + g;
#pragma unroll
        for (int nt = 0; nt < 8; nt++) {
            int col = bn + wn + nt * 8 + tg * 2;
            float b0 = bias[col], b1 = bias[col + 1];
            float2 v0 = make_float2(acc[mt][nt][0] + b0, acc[mt][nt][1] + b1);
            float2 v1 = make_float2(acc[mt][nt][2] + b0, acc[mt][nt][3] + b1);
            *reinterpret_cast<float2*>(&C[(long)row0 * N + col])       = v0;
            *reinterpret_cast<float2*>(&C[(long)(row0 + 8) * N + col]) = v1;
        }
    }
}

// ---------------- persistent GRU recurrence ----------------
// H in {512, 1024}. NCTA = H/8 CTAs, each owns 8 hidden columns (gate cols j, H+j, 2H+j).
// 8 warps split K = H into 8 chunks; partial gh reduced through SMEM; 1 grid barrier / step.
template <int H, int LAYER>
__global__ void rec_kernel(const float* __restrict__ gx, const __half* __restrict__ whh,
                           const float* __restrict__ bhh, float* __restrict__ outp,
                           unsigned int* __restrict__ barctr) {
    constexpr int K = H;
    constexpr int Kc = K / 8;           // per-warp K chunk
    constexpr int KI = Kc / 16;         // mma k-iterations per warp
    constexpr int NCTA = H / 8;
    constexpr int GA = 3 * H;

    extern __shared__ unsigned char smem[];
    uint32_t* sB  = reinterpret_cast<uint32_t*>(smem);                 // [8][KI][3][2][32]
    float*    sRed = reinterpret_cast<float*>(smem + (size_t)8 * KI * 3 * 2 * 32 * 4); // [8][64][24]

    const int tid = threadIdx.x;
    const int w = tid >> 5, lane = tid & 31;
    const int g = lane >> 2, tg = lane & 3;
    const int j0 = blockIdx.x * 8;

    // Stage this CTA's W_hh fragments into SMEM once (reused 256 steps).
#pragma unroll
    for (int i = 0; i < KI; i++) {
        int k0 = w * Kc + i * 16;
#pragma unroll
        for (int gate = 0; gate < 3; gate++) {
            int n = gate * H + j0 + g;
            const __half* p = whh + (long)n * K + k0 + tg * 2;
            uint32_t b0 = ld32h(p);
            uint32_t b1 = ld32h(p + 8);
            int base = (((w * KI + i) * 3 + gate) * 2) * 32 + lane;
            sB[base]      = b0;
            sB[base + 32] = b1;
        }
    }

    // Zero h0 slice (this CTA's columns, all 64 rows), both precisions, buffer 0.
    for (int v = tid; v < 512; v += 256) {
        int b = v >> 3, jl = v & 7;
        d_hbuf16[0][b * H + j0 + jl] = __float2half(0.0f);
        d_hbuf32[0][b * H + j0 + jl] = 0.0f;
    }

    unsigned int ibar = 0;
    gridbar(barctr, (++ibar) * NCTA);   // h0 + W staging visible everywhere

    for (int t = 0; t < TT; t++) {
        const int cur = t & 1, nxt = cur ^ 1;
        const __half* hA = d_hbuf16[cur];

        float acc[12][4];
#pragma unroll
        for (int q = 0; q < 12; q++)
#pragma unroll
            for (int e = 0; e < 4; e++) acc[q][e] = 0.0f;

        for (int i = 0; i < KI; i++) {
            int k0 = w * Kc + i * 16;
            uint32_t a[4][4];
#pragma unroll
            for (int mt = 0; mt < 4; mt++) {
                int r0 = mt * 16 + g;
                const __half* pa = hA + (long)r0 * H + k0 + tg * 2;
                const __half* pb = hA + (long)(r0 + 8) * H + k0 + tg * 2;
                a[mt][0] = ld32h(pa);
                a[mt][1] = ld32h(pb);
                a[mt][2] = ld32h(pa + 8);
                a[mt][3] = ld32h(pb + 8);
            }
#pragma unroll
            for (int gate = 0; gate < 3; gate++) {
                int base = (((w * KI + i) * 3 + gate) * 2) * 32 + lane;
                uint32_t b[2] = { sB[base], sB[base + 32] };
#pragma unroll
                for (int mt = 0; mt < 4; mt++) mma16816(acc[mt * 3 + gate], a[mt], b);
            }
        }

        // Write per-warp partials to SMEM.
#pragma unroll
        for (int mt = 0; mt < 4; mt++) {
            int row = mt * 16 + g;
#pragma unroll
            for (int gate = 0; gate < 3; gate++) {
                float* c = acc[mt * 3 + gate];
                int col = gate * 8 + tg * 2;
                *reinterpret_cast<float2*>(&sRed[((w * 64) + row) * 24 + col])     = make_float2(c[0], c[1]);
                *reinterpret_cast<float2*>(&sRed[((w * 64) + row + 8) * 24 + col]) = make_float2(c[2], c[3]);
            }
        }
        __syncthreads();

        // Gate math: 512 h-values, 2 per thread.
#pragma unroll
        for (int v = 0; v < 2; v++) {
            int idx = tid + v * 256;      // 0..511
            int b = idx >> 3, jl = idx & 7, j = j0 + jl;
            float hr = 0.f, hz = 0.f, hn = 0.f;
#pragma unroll
            for (int ww = 0; ww < 8; ww++) {
                const float* rr = &sRed[(ww * 64 + b) * 24];
                hr += rr[jl];
                hz += rr[8 + jl];
                hn += rr[16 + jl];
            }
            hr += bhh[j];
            hz += bhh[H + j];
            hn += bhh[2 * H + j];
            const float* gxr = gx + ((long)b * TT + t) * GA;
            float xr = gxr[j], xz = gxr[H + j], xn = gxr[2 * H + j];
            float r = sigmoidf_(xr + hr);
            float z = sigmoidf_(xz + hz);
            float n = tanhf(xn + r * hn);
            float hprev = d_hbuf32[cur][b * H + j];
            float hnew = (1.0f - z) * n + z * hprev;
            d_hbuf32[nxt][b * H + j] = hnew;
            d_hbuf16[nxt][b * H + j] = __float2half(hnew);
            if (LAYER == 1) {
                d_h1seq[((long)b * TT + t) * H + j] = __float2half(fmaxf(hnew, 0.0f));
            } else {
                outp[((long)b * TT + t) * H + j] = hnew;
            }
        }
        gridbar(barctr, (++ibar) * NCTA);
    }
}

// ---------------- launch ----------------
extern "C" void kernel_launch(void* const* d_in, const int* in_sizes, int n_in,
                              void* d_out, int out_size) {
    const float* x    = (const float*)d_in[0];
    const float* wih1 = (const float*)d_in[1];
    const float* whh1 = (const float*)d_in[2];
    const float* bih1 = (const float*)d_in[3];
    const float* bhh1 = (const float*)d_in[4];
    const float* wih2 = (const float*)d_in[5];
    const float* whh2 = (const float*)d_in[6];
    const float* bih2 = (const float*)d_in[7];
    const float* bhh2 = (const float*)d_in[8];
    float* out = (float*)d_out;

    // Resolve device-scratch symbol addresses (host API, capture-safe, no allocs).
    void *p_xh, *p_wih1, *p_whh1, *p_wih2, *p_whh2, *p_gx1, *p_gx2, *p_h1, *p_bar1, *p_bar2;
    cudaGetSymbolAddress(&p_xh, d_xh);
    cudaGetSymbolAddress(&p_wih1, d_wih1);
    cudaGetSymbolAddress(&p_whh1, d_whh1);
    cudaGetSymbolAddress(&p_wih2, d_wih2);
    cudaGetSymbolAddress(&p_whh2, d_whh2);
    cudaGetSymbolAddress(&p_gx1, d_gx1);
    cudaGetSymbolAddress(&p_gx2, d_gx2);
    cudaGetSymbolAddress(&p_h1, d_h1seq);
    cudaGetSymbolAddress(&p_bar1, d_bar1);
    cudaGetSymbolAddress(&p_bar2, d_bar2);

    const int SMEM1 = 8 * 4 * 3 * 2 * 32 * 4 + 8 * 64 * 24 * 4;   // 24576 + 49152 = 73728
    const int SMEM2 = 8 * 8 * 3 * 2 * 32 * 4 + 8 * 64 * 24 * 4;   // 49152 + 49152 = 98304
    cudaFuncSetAttribute(rec_kernel<512, 1>, cudaFuncAttributeMaxDynamicSharedMemorySize, SMEM1);
    cudaFuncSetAttribute(rec_kernel<1024, 2>, cudaFuncAttributeMaxDynamicSharedMemorySize, SMEM2);

    // 1) fp16 conversions + barrier reset
    prep_kernel<<<2048, 256>>>(x, wih1, whh1, wih2, whh2);

    // 2) gx1 = x @ W_ih1^T + b_ih1 : [16384,1536], K=1024
    {
        dim3 grid(1536 / 256, 16384 / 64);
        gemm_tn_kernel<<<grid, 256>>>((const __half*)p_xh, (const __half*)p_wih1,
                                      bih1, (float*)p_gx1, 16384, 1536, 1024);
    }

    // 3) layer-1 recurrence (writes relu(h1) fp16 sequence)
    rec_kernel<512, 1><<<512 / 8, 256, SMEM1>>>((const float*)p_gx1, (const __half*)p_whh1,
                                                bhh1, nullptr, (unsigned int*)p_bar1);

    // 4) gx2 = relu(h1) @ W_ih2^T + b_ih2 : [16384,3072], K=512
    {
        dim3 grid(3072 / 256, 16384 / 64);
        gemm_tn_kernel<<<grid, 256>>>((const __half*)p_h1, (const __half*)p_wih2,
                                      bih2, (float*)p_gx2, 16384, 3072, 512);
    }

    // 5) layer-2 recurrence (writes fp32 output)
    rec_kernel<1024, 2><<<1024 / 8, 256, SMEM2>>>((const float*)p_gx2, (const __half*)p_whh2,
                                                  bhh2, out, (unsigned int*)p_bar2);
}

// round 3
// speedup vs baseline: 1.3221x; 1.3221x over previous
#include <cuda_runtime.h>
#include <cuda_fp16.h>
#include <math.h>
#include <stdint.h>

#define BB 64
#define TT 256
#define IIN 1024
#define HHID 512

// ---------------- device scratch (static: no allocations allowed) ----------------
__device__ __half d_xh[16384u * 1024u];
__device__ __half d_wih1[1536u * 1024u];
__device__ __half d_whh1[1536u * 512u];
__device__ __half d_wih2[3072u * 512u];
__device__ __half d_whh2[3072u * 1024u];
__device__ float  d_gx1[16384u * 1536u];
__device__ float  d_gx2[16384u * 3072u];
__device__ __half d_h1seq[16384u * 512u];
__device__ __half d_hbuf16[2][64 * 1024];
__device__ unsigned int d_bar1;
__device__ unsigned int d_bar2;

// ---------------- helpers ----------------
__device__ __forceinline__ uint32_t ld32h(const __half* p) {
    return *reinterpret_cast<const uint32_t*>(p);
}

__device__ __forceinline__ void mma16816(float* c, const uint32_t* a, const uint32_t* b) {
    asm volatile(
        "mma.sync.aligned.m16n8k16.row.col.f32.f16.f16.f32 "
        "{%0,%1,%2,%3}, {%4,%5,%6,%7}, {%8,%9}, {%0,%1,%2,%3};\n"
        : "+f"(c[0]), "+f"(c[1]), "+f"(c[2]), "+f"(c[3])
        : "r"(a[0]), "r"(a[1]), "r"(a[2]), "r"(a[3]), "r"(b[0]), "r"(b[1]));
}

__device__ __forceinline__ float sigm(float x) {
    return 1.0f / (1.0f + __expf(-x));
}
__device__ __forceinline__ float tanh_fast(float x) {
    return 2.0f / (1.0f + __expf(-2.0f * x)) - 1.0f;
}

__device__ __forceinline__ void cp16(void* s, const void* g) {
    unsigned sa = (unsigned)__cvta_generic_to_shared(s);
    asm volatile("cp.async.cg.shared.global [%0], [%1], 16;\n" :: "r"(sa), "l"(g));
}
__device__ __forceinline__ void cp_commit() { asm volatile("cp.async.commit_group;\n"); }
__device__ __forceinline__ void cp_wait0()  { asm volatile("cp.async.wait_group 0;\n"); }

// Grid barrier: release-add + acquire-poll (no membar.gl, no nanosleep).
__device__ __forceinline__ void gridbar(unsigned int* ctr, unsigned int target) {
    __syncthreads();
    if (threadIdx.x == 0) {
        asm volatile("red.release.gpu.global.add.u32 [%0], 1;\n" :: "l"(ctr) : "memory");
        unsigned int v;
        do {
            asm volatile("ld.acquire.gpu.global.u32 %0, [%1];\n" : "=r"(v) : "l"(ctr) : "memory");
        } while (v < target);
    }
    __syncthreads();
}

// ---------------- prep ----------------
__global__ void prep_kernel(const float* __restrict__ x,
                            const float* __restrict__ wih1, const float* __restrict__ whh1,
                            const float* __restrict__ wih2, const float* __restrict__ whh2) {
    long idx = (long)blockIdx.x * blockDim.x + threadIdx.x;
    long stride = (long)gridDim.x * blockDim.x;
    if (idx == 0) { d_bar1 = 0u; d_bar2 = 0u; }
    for (long i = idx; i < 16384L * 1024L; i += stride) d_xh[i]   = __float2half(x[i]);
    for (long i = idx; i < 1536L * 1024L;  i += stride) d_wih1[i] = __float2half(wih1[i]);
    for (long i = idx; i < 1536L * 512L;   i += stride) d_whh1[i] = __float2half(whh1[i]);
    for (long i = idx; i < 3072L * 512L;   i += stride) d_wih2[i] = __float2half(wih2[i]);
    for (long i = idx; i < 3072L * 1024L;  i += stride) d_whh2[i] = __float2half(whh2[i]);
}

// ---------------- pipelined SMEM GEMM: C[M,N] = A[M,K] @ W[N,K]^T + bias ----------------
// CTA 128x128, K-tile 32, cp.async double-buffered, padded SMEM stride 40 halfs.
#define SSTR 40
__global__ __launch_bounds__(256) void gemm_tn_kernel(
        const __half* __restrict__ A, const __half* __restrict__ W,
        const float* __restrict__ bias, float* __restrict__ C,
        int M, int N, int K) {
    __shared__ __half sA[2][128 * SSTR];
    __shared__ __half sB[2][128 * SSTR];

    const int bn = blockIdx.x * 128;
    const int bm = blockIdx.y * 128;
    const int tid = threadIdx.x;
    const int w = tid >> 5, lane = tid & 31;
    const int g = lane >> 2, tg = lane & 3;
    const int wm = (w >> 2) * 64;   // 0 or 64
    const int wn = (w & 3) * 32;    // 0,32,64,96

    float acc[4][4][4];
#pragma unroll
    for (int mt = 0; mt < 4; mt++)
#pragma unroll
        for (int nt = 0; nt < 4; nt++)
#pragma unroll
            for (int e = 0; e < 4; e++) acc[mt][nt][e] = 0.0f;

    const int KT = K >> 5;

    // prologue: tile 0
    {
#pragma unroll
        for (int c = 0; c < 2; c++) {
            int chunk = tid + c * 256;
            int r = chunk >> 2, cc = chunk & 3;
            cp16(&sA[0][r * SSTR + cc * 8], A + (long)(bm + r) * K + cc * 8);
            cp16(&sB[0][r * SSTR + cc * 8], W + (long)(bn + r) * K + cc * 8);
        }
        cp_commit();
    }

    for (int kt = 0; kt < KT; kt++) {
        cp_wait0();
        __syncthreads();
        if (kt + 1 < KT) {
            int k0 = (kt + 1) << 5;
            int nb = (kt + 1) & 1;
#pragma unroll
            for (int c = 0; c < 2; c++) {
                int chunk = tid + c * 256;
                int r = chunk >> 2, cc = chunk & 3;
                cp16(&sA[nb][r * SSTR + cc * 8], A + (long)(bm + r) * K + k0 + cc * 8);
                cp16(&sB[nb][r * SSTR + cc * 8], W + (long)(bn + r) * K + k0 + cc * 8);
            }
            cp_commit();
        }
        const __half* a_s = sA[kt & 1];
        const __half* b_s = sB[kt & 1];
#pragma unroll
        for (int ks = 0; ks < 2; ks++) {
            const int kk = ks * 16;
            uint32_t af[4][4];
#pragma unroll
            for (int mt = 0; mt < 4; mt++) {
                int r = wm + mt * 16 + g;
                af[mt][0] = ld32h(a_s + r * SSTR + kk + tg * 2);
                af[mt][1] = ld32h(a_s + (r + 8) * SSTR + kk + tg * 2);
                af[mt][2] = ld32h(a_s + r * SSTR + kk + tg * 2 + 8);
                af[mt][3] = ld32h(a_s + (r + 8) * SSTR + kk + tg * 2 + 8);
            }
            uint32_t bf[4][2];
#pragma unroll
            for (int nt = 0; nt < 4; nt++) {
                int n = wn + nt * 8 + g;
                bf[nt][0] = ld32h(b_s + n * SSTR + kk + tg * 2);
                bf[nt][1] = ld32h(b_s + n * SSTR + kk + tg * 2 + 8);
            }
#pragma unroll
            for (int mt = 0; mt < 4; mt++)
#pragma unroll
                for (int nt = 0; nt < 4; nt++) mma16816(acc[mt][nt], af[mt], bf[nt]);
        }
    }

#pragma unroll
    for (int mt = 0; mt < 4; mt++) {
        int row0 = bm + wm + mt * 16 + g;
#pragma unroll
        for (int nt = 0; nt < 4; nt++) {
            int col = bn + wn + nt * 8 + tg * 2;
            float b0 = bias[col], b1 = bias[col + 1];
            float2 v0 = make_float2(acc[mt][nt][0] + b0, acc[mt][nt][1] + b1);
            float2 v1 = make_float2(acc[mt][nt][2] + b0, acc[mt][nt][3] + b1);
            *reinterpret_cast<float2*>(&C[(long)row0 * N + col])       = v0;
            *reinterpret_cast<float2*>(&C[(long)(row0 + 8) * N + col]) = v1;
        }
    }
}

// ---------------- persistent GRU recurrence ----------------
// NCTA = H/8 CTAs; 8 warps = 4 K-chunks x 2 M-halves; register-resident h_prev;
// 4-way SMEM reduction; gx prefetch; release/acquire barrier; 1 barrier/step.
template <int H, int LAYER>
__global__ __launch_bounds__(256) void rec_kernel(
        const float* __restrict__ gx, const __half* __restrict__ whh,
        const float* __restrict__ bhh, float* __restrict__ outp,
        unsigned int* __restrict__ barctr) {
    constexpr int K = H;
    constexpr int Kw = K / 4;            // per-K-chunk width
    constexpr int KI = Kw / 16;          // mma k-iters per warp
    constexpr int NCTA = H / 8;
    constexpr int GA = 3 * H;

    extern __shared__ unsigned char smem[];
    uint32_t* sB  = reinterpret_cast<uint32_t*>(smem);                       // [4][KI][3][2][32]
    float*    sRed = reinterpret_cast<float*>(smem + (size_t)4 * KI * 3 * 2 * 32 * 4); // [4][64][24]

    const int tid = threadIdx.x;
    const int w = tid >> 5, lane = tid & 31;
    const int km = w & 3, mh = w >> 2;   // K-chunk, M-half
    const int g = lane >> 2, tg = lane & 3;
    const int j0 = blockIdx.x * 8;
    const int mrow = mh * 32;

    // Stage W_hh fragments (mh==0 warps), reused 256 steps.
    if (mh == 0) {
#pragma unroll
        for (int i = 0; i < KI; i++) {
            int k0 = km * Kw + i * 16;
#pragma unroll
            for (int gate = 0; gate < 3; gate++) {
                int n = gate * H + j0 + g;
                const __half* p = whh + (long)n * K + k0 + tg * 2;
                int base = (((km * KI + i) * 3 + gate) * 2) * 32 + lane;
                sB[base]      = ld32h(p);
                sB[base + 32] = ld32h(p + 8);
            }
        }
    }

    // Per-thread gate-state: thread handles idx = tid and tid+256.
    float hp[2] = {0.0f, 0.0f};
    float br[2], bz[2], bn_[2];
    int   bidx[2], jidx[2];
    const float* gxbase[2];
#pragma unroll
    for (int v = 0; v < 2; v++) {
        int idx = tid + v * 256;
        int b = idx >> 3, jl = idx & 7, j = j0 + jl;
        bidx[v] = b; jidx[v] = j;
        br[v]  = bhh[j];
        bz[v]  = bhh[H + j];
        bn_[v] = bhh[2 * H + j];
        gxbase[v] = gx + (long)b * TT * GA + j;
        // zero h0 slice (fp16 buffer 0, own columns)
        d_hbuf16[0][b * H + j] = __float2half(0.0f);
    }

    unsigned int ibar = 0;
    gridbar(barctr, (++ibar) * NCTA);

    for (int t = 0; t < TT; t++) {
        const int cur = t & 1, nxt = cur ^ 1;
        const __half* hA = d_hbuf16[cur];

        // prefetch gx for this step (independent of h)
        float xr[2], xz[2], xn[2];
#pragma unroll
        for (int v = 0; v < 2; v++) {
            const float* p = gxbase[v] + (long)t * GA;
            xr[v] = __ldg(p);
            xz[v] = __ldg(p + H);
            xn[v] = __ldg(p + 2 * H);
        }

        float acc[6][4];
#pragma unroll
        for (int q = 0; q < 6; q++)
#pragma unroll
            for (int e = 0; e < 4; e++) acc[q][e] = 0.0f;

#pragma unroll
        for (int i = 0; i < KI; i++) {
            int k0 = km * Kw + i * 16;
            uint32_t a[2][4];
#pragma unroll
            for (int mt = 0; mt < 2; mt++) {
                int r0 = mrow + mt * 16 + g;
                const __half* pa = hA + (long)r0 * H + k0 + tg * 2;
                const __half* pb = pa + 8 * H;
                a[mt][0] = ld32h(pa);
                a[mt][1] = ld32h(pb);
                a[mt][2] = ld32h(pa + 8);
                a[mt][3] = ld32h(pb + 8);
            }
#pragma unroll
            for (int gate = 0; gate < 3; gate++) {
                int base = (((km * KI + i) * 3 + gate) * 2) * 32 + lane;
                uint32_t b[2] = { sB[base], sB[base + 32] };
#pragma unroll
                for (int mt = 0; mt < 2; mt++) mma16816(acc[mt * 3 + gate], a[mt], b);
            }
        }

        // per-K-chunk partials -> SMEM
#pragma unroll
        for (int mt = 0; mt < 2; mt++) {
            int row = mrow + mt * 16 + g;
#pragma unroll
            for (int gate = 0; gate < 3; gate++) {
                float* c = acc[mt * 3 + gate];
                int col = gate * 8 + tg * 2;
                *reinterpret_cast<float2*>(&sRed[(km * 64 + row) * 24 + col])     = make_float2(c[0], c[1]);
                *reinterpret_cast<float2*>(&sRed[(km * 64 + row + 8) * 24 + col]) = make_float2(c[2], c[3]);
            }
        }
        __syncthreads();

        // gate math: 2 h-values per thread, h_prev in registers
#pragma unroll
        for (int v = 0; v < 2; v++) {
            int idx = tid + v * 256;
            int b = bidx[v], jl = idx & 7, j = jidx[v];
            float hr = br[v], hz = bz[v], hn = bn_[v];
#pragma unroll
            for (int kk = 0; kk < 4; kk++) {
                const float* rr = &sRed[(kk * 64 + b) * 24];
                hr += rr[jl];
                hz += rr[8 + jl];
                hn += rr[16 + jl];
            }
            float r = sigm(xr[v] + hr);
            float z = sigm(xz[v] + hz);
            float n = tanh_fast(fmaf(r, hn, xn[v]));
            float hnew = fmaf(z, hp[v] - n, n);
            hp[v] = hnew;
            d_hbuf16[nxt][b * H + j] = __float2half(hnew);
            if (LAYER == 1) {
                d_h1seq[((long)b * TT + t) * H + j] = __float2half(fmaxf(hnew, 0.0f));
            } else {
                outp[((long)b * TT + t) * H + j] = hnew;
            }
        }
        gridbar(barctr, (++ibar) * NCTA);
    }
}

// ---------------- launch ----------------
extern "C" void kernel_launch(void* const* d_in, const int* in_sizes, int n_in,
                              void* d_out, int out_size) {
    const float* x    = (const float*)d_in[0];
    const float* wih1 = (const float*)d_in[1];
    const float* whh1 = (const float*)d_in[2];
    const float* bih1 = (const float*)d_in[3];
    const float* bhh1 = (const float*)d_in[4];
    const float* wih2 = (const float*)d_in[5];
    const float* whh2 = (const float*)d_in[6];
    const float* bih2 = (const float*)d_in[7];
    const float* bhh2 = (const float*)d_in[8];
    float* out = (float*)d_out;

    void *p_xh, *p_wih1, *p_whh1, *p_wih2, *p_whh2, *p_gx1, *p_gx2, *p_h1, *p_bar1, *p_bar2;
    cudaGetSymbolAddress(&p_xh, d_xh);
    cudaGetSymbolAddress(&p_wih1, d_wih1);
    cudaGetSymbolAddress(&p_whh1, d_whh1);
    cudaGetSymbolAddress(&p_wih2, d_wih2);
    cudaGetSymbolAddress(&p_whh2, d_whh2);
    cudaGetSymbolAddress(&p_gx1, d_gx1);
    cudaGetSymbolAddress(&p_gx2, d_gx2);
    cudaGetSymbolAddress(&p_h1, d_h1seq);
    cudaGetSymbolAddress(&p_bar1, d_bar1);
    cudaGetSymbolAddress(&p_bar2, d_bar2);

    // rec smem: sB = 4*KI*3*2*32*4 bytes; sRed = 4*64*24*4 = 24576
    const int SMEM1 = 4 * 8  * 3 * 2 * 32 * 4 + 24576;   // 24576 + 24576 = 49152
    const int SMEM2 = 4 * 16 * 3 * 2 * 32 * 4 + 24576;   // 49152 + 24576 = 73728
    cudaFuncSetAttribute(rec_kernel<512, 1>,  cudaFuncAttributeMaxDynamicSharedMemorySize, SMEM1);
    cudaFuncSetAttribute(rec_kernel<1024, 2>, cudaFuncAttributeMaxDynamicSharedMemorySize, SMEM2);

    prep_kernel<<<2048, 256>>>(x, wih1, whh1, wih2, whh2);

    {   // gx1 = x @ W_ih1^T + b_ih1 : [16384,1536], K=1024
        dim3 grid(1536 / 128, 16384 / 128);
        gemm_tn_kernel<<<grid, 256>>>((const __half*)p_xh, (const __half*)p_wih1,
                                      bih1, (float*)p_gx1, 16384, 1536, 1024);
    }

    rec_kernel<512, 1><<<64, 256, SMEM1>>>((const float*)p_gx1, (const __half*)p_whh1,
                                           bhh1, nullptr, (unsigned int*)p_bar1);

    {   // gx2 = relu(h1) @ W_ih2^T + b_ih2 : [16384,3072], K=512
        dim3 grid(3072 / 128, 16384 / 128);
        gemm_tn_kernel<<<grid, 256>>>((const __half*)p_h1, (const __half*)p_wih2,
                                      bih2, (float*)p_gx2, 16384, 3072, 512);
    }

    rec_kernel<1024, 2><<<128, 256, SMEM2>>>((const float*)p_gx2, (const __half*)p_whh2,
                                             bhh2, out, (unsigned int*)p_bar2);
}

// round 4
// speedup vs baseline: 1.5787x; 1.1940x over previous
#include <cuda_runtime.h>
#include <cuda_fp16.h>
#include <math.h>
#include <stdint.h>

#define BB 64
#define TT 256
#define IIN 1024
#define HHID 512

// ---------------- device scratch (static: no allocations allowed) ----------------
__device__ __half d_xh[16384u * 1024u];
__device__ __half d_wih1[1536u * 1024u];
__device__ __half d_whh1[1536u * 512u];
__device__ __half d_wih2[3072u * 512u];
__device__ __half d_whh2[3072u * 1024u];
__device__ float  d_gx1[16384u * 1536u];
__device__ float  d_gx2[16384u * 3072u];
__device__ __half d_h1seq[16384u * 512u];
__device__ __half d_hbuf16[2][64 * 1024];
__device__ unsigned int d_bar1;
__device__ unsigned int d_bar2;

// ---------------- helpers ----------------
__device__ __forceinline__ uint32_t ld32h(const __half* p) {
    return *reinterpret_cast<const uint32_t*>(p);
}

__device__ __forceinline__ void mma16816(float* c, const uint32_t* a, const uint32_t* b) {
    asm volatile(
        "mma.sync.aligned.m16n8k16.row.col.f32.f16.f16.f32 "
        "{%0,%1,%2,%3}, {%4,%5,%6,%7}, {%8,%9}, {%0,%1,%2,%3};\n"
        : "+f"(c[0]), "+f"(c[1]), "+f"(c[2]), "+f"(c[3])
        : "r"(a[0]), "r"(a[1]), "r"(a[2]), "r"(a[3]), "r"(b[0]), "r"(b[1]));
}

__device__ __forceinline__ void ldsm_x4(uint32_t* r, const __half* p) {
    unsigned sa = (unsigned)__cvta_generic_to_shared(p);
    asm volatile("ldmatrix.sync.aligned.m8n8.x4.shared.b16 {%0,%1,%2,%3}, [%4];\n"
                 : "=r"(r[0]), "=r"(r[1]), "=r"(r[2]), "=r"(r[3]) : "r"(sa));
}

__device__ __forceinline__ float sigm(float x) {
    return 1.0f / (1.0f + __expf(-x));
}
__device__ __forceinline__ float tanh_fast(float x) {
    return 2.0f / (1.0f + __expf(-2.0f * x)) - 1.0f;
}

__device__ __forceinline__ void cp16(void* s, const void* g) {
    unsigned sa = (unsigned)__cvta_generic_to_shared(s);
    asm volatile("cp.async.cg.shared.global [%0], [%1], 16;\n" :: "r"(sa), "l"(g));
}
__device__ __forceinline__ void cp_commit() { asm volatile("cp.async.commit_group;\n"); }
__device__ __forceinline__ void cp_wait0()  { asm volatile("cp.async.wait_group 0;\n"); }

// Grid barrier: release-add + acquire-poll.
__device__ __forceinline__ void gridbar(unsigned int* ctr, unsigned int target) {
    __syncthreads();
    if (threadIdx.x == 0) {
        asm volatile("red.release.gpu.global.add.u32 [%0], 1;\n" :: "l"(ctr) : "memory");
        unsigned int v;
        do {
            asm volatile("ld.acquire.gpu.global.u32 %0, [%1];\n" : "=r"(v) : "l"(ctr) : "memory");
        } while (v < target);
    }
    __syncthreads();
}

// ---------------- prep ----------------
__global__ void prep_kernel(const float* __restrict__ x,
                            const float* __restrict__ wih1, const float* __restrict__ whh1,
                            const float* __restrict__ wih2, const float* __restrict__ whh2) {
    long idx = (long)blockIdx.x * blockDim.x + threadIdx.x;
    long stride = (long)gridDim.x * blockDim.x;
    if (idx == 0) { d_bar1 = 0u; d_bar2 = 0u; }
    for (long i = idx; i < 16384L * 1024L; i += stride) d_xh[i]   = __float2half(x[i]);
    for (long i = idx; i < 1536L * 1024L;  i += stride) d_wih1[i] = __float2half(wih1[i]);
    for (long i = idx; i < 1536L * 512L;   i += stride) d_whh1[i] = __float2half(whh1[i]);
    for (long i = idx; i < 3072L * 512L;   i += stride) d_wih2[i] = __float2half(wih2[i]);
    for (long i = idx; i < 3072L * 1024L;  i += stride) d_whh2[i] = __float2half(whh2[i]);
}

// ---------------- pipelined SMEM GEMM (unchanged from R3) ----------------
#define SSTR 40
__global__ __launch_bounds__(256) void gemm_tn_kernel(
        const __half* __restrict__ A, const __half* __restrict__ W,
        const float* __restrict__ bias, float* __restrict__ C,
        int M, int N, int K) {
    __shared__ __half sA[2][128 * SSTR];
    __shared__ __half sB[2][128 * SSTR];

    const int bn = blockIdx.x * 128;
    const int bm = blockIdx.y * 128;
    const int tid = threadIdx.x;
    const int w = tid >> 5, lane = tid & 31;
    const int g = lane >> 2, tg = lane & 3;
    const int wm = (w >> 2) * 64;
    const int wn = (w & 3) * 32;

    float acc[4][4][4];
#pragma unroll
    for (int mt = 0; mt < 4; mt++)
#pragma unroll
        for (int nt = 0; nt < 4; nt++)
#pragma unroll
            for (int e = 0; e < 4; e++) acc[mt][nt][e] = 0.0f;

    const int KT = K >> 5;
    {
#pragma unroll
        for (int c = 0; c < 2; c++) {
            int chunk = tid + c * 256;
            int r = chunk >> 2, cc = chunk & 3;
            cp16(&sA[0][r * SSTR + cc * 8], A + (long)(bm + r) * K + cc * 8);
            cp16(&sB[0][r * SSTR + cc * 8], W + (long)(bn + r) * K + cc * 8);
        }
        cp_commit();
    }

    for (int kt = 0; kt < KT; kt++) {
        cp_wait0();
        __syncthreads();
        if (kt + 1 < KT) {
            int k0 = (kt + 1) << 5;
            int nb = (kt + 1) & 1;
#pragma unroll
            for (int c = 0; c < 2; c++) {
                int chunk = tid + c * 256;
                int r = chunk >> 2, cc = chunk & 3;
                cp16(&sA[nb][r * SSTR + cc * 8], A + (long)(bm + r) * K + k0 + cc * 8);
                cp16(&sB[nb][r * SSTR + cc * 8], W + (long)(bn + r) * K + k0 + cc * 8);
            }
            cp_commit();
        }
        const __half* a_s = sA[kt & 1];
        const __half* b_s = sB[kt & 1];
#pragma unroll
        for (int ks = 0; ks < 2; ks++) {
            const int kk = ks * 16;
            uint32_t af[4][4];
#pragma unroll
            for (int mt = 0; mt < 4; mt++) {
                int r = wm + mt * 16 + g;
                af[mt][0] = ld32h(a_s + r * SSTR + kk + tg * 2);
                af[mt][1] = ld32h(a_s + (r + 8) * SSTR + kk + tg * 2);
                af[mt][2] = ld32h(a_s + r * SSTR + kk + tg * 2 + 8);
                af[mt][3] = ld32h(a_s + (r + 8) * SSTR + kk + tg * 2 + 8);
            }
            uint32_t bf[4][2];
#pragma unroll
            for (int nt = 0; nt < 4; nt++) {
                int n = wn + nt * 8 + g;
                bf[nt][0] = ld32h(b_s + n * SSTR + kk + tg * 2);
                bf[nt][1] = ld32h(b_s + n * SSTR + kk + tg * 2 + 8);
            }
#pragma unroll
            for (int mt = 0; mt < 4; mt++)
#pragma unroll
                for (int nt = 0; nt < 4; nt++) mma16816(acc[mt][nt], af[mt], bf[nt]);
        }
    }

#pragma unroll
    for (int mt = 0; mt < 4; mt++) {
        int row0 = bm + wm + mt * 16 + g;
#pragma unroll
        for (int nt = 0; nt < 4; nt++) {
            int col = bn + wn + nt * 8 + tg * 2;
            float b0 = bias[col], b1 = bias[col + 1];
            float2 v0 = make_float2(acc[mt][nt][0] + b0, acc[mt][nt][1] + b1);
            float2 v1 = make_float2(acc[mt][nt][2] + b0, acc[mt][nt][3] + b1);
            *reinterpret_cast<float2*>(&C[(long)row0 * N + col])       = v0;
            *reinterpret_cast<float2*>(&C[(long)(row0 + 8) * N + col]) = v1;
        }
    }
}

// ---------------- persistent GRU recurrence (SMEM-staged h + ldmatrix) ----------------
// NCTA = H/8 CTAs; 8 warps = 4 K-chunks x 2 M-halves. Per step: cp.async h tile into
// SMEM (padded stride => conflict-free LDSM), ldmatrix a-frags, LDS.64 b-frags,
// 4-way SMEM reduction, register h_prev, 1 grid barrier/step.
template <int H, int LAYER>
__global__ __launch_bounds__(256) void rec_kernel(
        const float* __restrict__ gx, const __half* __restrict__ whh,
        const float* __restrict__ bhh, float* __restrict__ outp,
        unsigned int* __restrict__ barctr) {
    constexpr int K = H;
    constexpr int Kw = K / 4;
    constexpr int KI = Kw / 16;
    constexpr int NCTA = H / 8;
    constexpr int GA = 3 * H;
    constexpr int STRIDE = H + 8;               // halfs; +16B pad -> LDSM conflict-free
    constexpr int CH_ROW = H / 8;               // 16B chunks per h row
    constexpr int LOG_CH = (H == 512) ? 6 : 7;  // log2(CH_ROW)

    extern __shared__ unsigned char smem[];
    __half*   sH   = reinterpret_cast<__half*>(smem);                               // [64][STRIDE]
    uint32_t* sB   = reinterpret_cast<uint32_t*>(smem + (size_t)64 * STRIDE * 2);   // [4*KI*3][32][2]
    float*    sRed = reinterpret_cast<float*>(smem + (size_t)64 * STRIDE * 2 + (size_t)4 * KI * 3 * 64 * 4); // [4][64][24]

    const int tid = threadIdx.x;
    const int w = tid >> 5, lane = tid & 31;
    const int km = w & 3, mh = w >> 2;
    const int g = lane >> 2, tg = lane & 3;
    const int j0 = blockIdx.x * 8;
    const int mrow = mh * 32;
    const int lr = lane & 15, lc = (lane >> 4) << 3;   // ldmatrix row/col split

    // Stage W_hh fragments once (pairs adjacent for LDS.64).
    if (mh == 0) {
#pragma unroll
        for (int i = 0; i < KI; i++) {
            int k0 = km * Kw + i * 16;
#pragma unroll
            for (int gate = 0; gate < 3; gate++) {
                int n = gate * H + j0 + g;
                const __half* p = whh + (long)n * K + k0 + tg * 2;
                int base2 = ((((km * KI + i) * 3 + gate) * 32) + lane) * 2;
                sB[base2]     = ld32h(p);
                sB[base2 + 1] = ld32h(p + 8);
            }
        }
    }

    float hp[2] = {0.0f, 0.0f};
    float br[2], bz[2], bn_[2];
    int   bidx[2], jidx[2];
    const float* gxbase[2];
#pragma unroll
    for (int v = 0; v < 2; v++) {
        int idx = tid + v * 256;
        int b = idx >> 3, jl = idx & 7, j = j0 + jl;
        bidx[v] = b; jidx[v] = j;
        br[v]  = bhh[j];
        bz[v]  = bhh[H + j];
        bn_[v] = bhh[2 * H + j];
        gxbase[v] = gx + (long)b * TT * GA + j;
        d_hbuf16[0][b * H + j] = __float2half(0.0f);
    }

    unsigned int ibar = 0;
    gridbar(barctr, (++ibar) * NCTA);

    for (int t = 0; t < TT; t++) {
        const int cur = t & 1, nxt = cur ^ 1;
        const __half* hA = d_hbuf16[cur];

        // Stage h tile [64 x H] -> SMEM, coalesced 16B chunks.
#pragma unroll
        for (int c = tid; c < 64 * CH_ROW; c += 256) {
            int r = c >> LOG_CH, cc = c & (CH_ROW - 1);
            cp16(&sH[r * STRIDE + cc * 8], hA + (long)r * H + cc * 8);
        }
        cp_commit();

        // Prefetch gx while cp.async is in flight.
        float xr[2], xz[2], xn[2];
#pragma unroll
        for (int v = 0; v < 2; v++) {
            const float* p = gxbase[v] + (long)t * GA;
            xr[v] = __ldg(p);
            xz[v] = __ldg(p + H);
            xn[v] = __ldg(p + 2 * H);
        }

        cp_wait0();
        __syncthreads();

        float acc[6][4];
#pragma unroll
        for (int q = 0; q < 6; q++)
#pragma unroll
            for (int e = 0; e < 4; e++) acc[q][e] = 0.0f;

#pragma unroll
        for (int i = 0; i < KI; i++) {
            int k0 = km * Kw + i * 16;
            uint32_t a[2][4];
#pragma unroll
            for (int mt = 0; mt < 2; mt++) {
                ldsm_x4(a[mt], sH + (mrow + mt * 16 + lr) * STRIDE + k0 + lc);
            }
#pragma unroll
            for (int gate = 0; gate < 3; gate++) {
                int base2 = ((((km * KI + i) * 3 + gate) * 32) + lane) * 2;
                uint2 bp = *reinterpret_cast<const uint2*>(&sB[base2]);
                uint32_t b[2] = { bp.x, bp.y };
#pragma unroll
                for (int mt = 0; mt < 2; mt++) mma16816(acc[mt * 3 + gate], a[mt], b);
            }
        }

#pragma unroll
        for (int mt = 0; mt < 2; mt++) {
            int row = mrow + mt * 16 + g;
#pragma unroll
            for (int gate = 0; gate < 3; gate++) {
                float* c = acc[mt * 3 + gate];
                int col = gate * 8 + tg * 2;
                *reinterpret_cast<float2*>(&sRed[(km * 64 + row) * 24 + col])     = make_float2(c[0], c[1]);
                *reinterpret_cast<float2*>(&sRed[(km * 64 + row + 8) * 24 + col]) = make_float2(c[2], c[3]);
            }
        }
        __syncthreads();

#pragma unroll
        for (int v = 0; v < 2; v++) {
            int idx = tid + v * 256;
            int b = bidx[v], jl = idx & 7, j = jidx[v];
            float hr = br[v], hz = bz[v], hn = bn_[v];
#pragma unroll
            for (int kk = 0; kk < 4; kk++) {
                const float* rr = &sRed[(kk * 64 + b) * 24];
                hr += rr[jl];
                hz += rr[8 + jl];
                hn += rr[16 + jl];
            }
            float r = sigm(xr[v] + hr);
            float z = sigm(xz[v] + hz);
            float n = tanh_fast(fmaf(r, hn, xn[v]));
            float hnew = fmaf(z, hp[v] - n, n);
            hp[v] = hnew;
            d_hbuf16[nxt][b * H + j] = __float2half(hnew);
            if (LAYER == 1) {
                d_h1seq[((long)b * TT + t) * H + j] = __float2half(fmaxf(hnew, 0.0f));
            } else {
                outp[((long)b * TT + t) * H + j] = hnew;
            }
        }
        gridbar(barctr, (++ibar) * NCTA);
    }
}

// ---------------- launch ----------------
extern "C" void kernel_launch(void* const* d_in, const int* in_sizes, int n_in,
                              void* d_out, int out_size) {
    const float* x    = (const float*)d_in[0];
    const float* wih1 = (const float*)d_in[1];
    const float* whh1 = (const float*)d_in[2];
    const float* bih1 = (const float*)d_in[3];
    const float* bhh1 = (const float*)d_in[4];
    const float* wih2 = (const float*)d_in[5];
    const float* whh2 = (const float*)d_in[6];
    const float* bih2 = (const float*)d_in[7];
    const float* bhh2 = (const float*)d_in[8];
    float* out = (float*)d_out;

    void *p_xh, *p_wih1, *p_whh1, *p_wih2, *p_whh2, *p_gx1, *p_gx2, *p_h1, *p_bar1, *p_bar2;
    cudaGetSymbolAddress(&p_xh, d_xh);
    cudaGetSymbolAddress(&p_wih1, d_wih1);
    cudaGetSymbolAddress(&p_whh1, d_whh1);
    cudaGetSymbolAddress(&p_wih2, d_wih2);
    cudaGetSymbolAddress(&p_whh2, d_whh2);
    cudaGetSymbolAddress(&p_gx1, d_gx1);
    cudaGetSymbolAddress(&p_gx2, d_gx2);
    cudaGetSymbolAddress(&p_h1, d_h1seq);
    cudaGetSymbolAddress(&p_bar1, d_bar1);
    cudaGetSymbolAddress(&p_bar2, d_bar2);

    // smem: sH + sB + sRed
    const int SMEM1 = 64 * (512 + 8) * 2  + 4 * 8  * 3 * 64 * 4 + 24576;  // 66560+24576+24576 = 115712
    const int SMEM2 = 64 * (1024 + 8) * 2 + 4 * 16 * 3 * 64 * 4 + 24576;  // 132096+49152+24576 = 205824
    cudaFuncSetAttribute(rec_kernel<512, 1>,  cudaFuncAttributeMaxDynamicSharedMemorySize, SMEM1);
    cudaFuncSetAttribute(rec_kernel<1024, 2>, cudaFuncAttributeMaxDynamicSharedMemorySize, SMEM2);

    prep_kernel<<<2048, 256>>>(x, wih1, whh1, wih2, whh2);

    {   // gx1 = x @ W_ih1^T + b_ih1 : [16384,1536], K=1024
        dim3 grid(1536 / 128, 16384 / 128);
        gemm_tn_kernel<<<grid, 256>>>((const __half*)p_xh, (const __half*)p_wih1,
                                      bih1, (float*)p_gx1, 16384, 1536, 1024);
    }

    rec_kernel<512, 1><<<64, 256, SMEM1>>>((const float*)p_gx1, (const __half*)p_whh1,
                                           bhh1, nullptr, (unsigned int*)p_bar1);

    {   // gx2 = relu(h1) @ W_ih2^T + b_ih2 : [16384,3072], K=512
        dim3 grid(3072 / 128, 16384 / 128);
        gemm_tn_kernel<<<grid, 256>>>((const __half*)p_h1, (const __half*)p_wih2,
                                      bih2, (float*)p_gx2, 16384, 3072, 512);
    }

    rec_kernel<1024, 2><<<128, 256, SMEM2>>>((const float*)p_gx2, (const __half*)p_whh2,
                                             bhh2, out, (unsigned int*)p_bar2);
}

// round 5
// speedup vs baseline: 1.9559x; 1.2389x over previous
#include <cuda_runtime.h>
#include <cuda_fp16.h>
#include <math.h>
#include <stdint.h>

#define BB 64
#define TT 256
#define IIN 1024
#define HHID 512

// ---------------- device scratch (static: no allocations allowed) ----------------
__device__ __half d_xh[16384u * 1024u];
__device__ __half d_wih1[1536u * 1024u];
__device__ __half d_whh1[1536u * 512u];
__device__ __half d_wih2[3072u * 512u];
__device__ __half d_whh2[3072u * 1024u];
__device__ float  d_gx1[16384u * 1536u];
__device__ float  d_gx2[16384u * 3072u];
__device__ __half d_h1seq[16384u * 512u];
__device__ __half d_hbuf16[2][64 * 1024];
__device__ unsigned int d_bar1[2];
__device__ unsigned int d_bar2[2];

// ---------------- helpers ----------------
__device__ __forceinline__ uint32_t ld32h(const __half* p) {
    return *reinterpret_cast<const uint32_t*>(p);
}

__device__ __forceinline__ void mma16816(float* c, const uint32_t* a, const uint32_t* b) {
    asm volatile(
        "mma.sync.aligned.m16n8k16.row.col.f32.f16.f16.f32 "
        "{%0,%1,%2,%3}, {%4,%5,%6,%7}, {%8,%9}, {%0,%1,%2,%3};\n"
        : "+f"(c[0]), "+f"(c[1]), "+f"(c[2]), "+f"(c[3])
        : "r"(a[0]), "r"(a[1]), "r"(a[2]), "r"(a[3]), "r"(b[0]), "r"(b[1]));
}

__device__ __forceinline__ void ldsm_x4(uint32_t* r, const __half* p) {
    unsigned sa = (unsigned)__cvta_generic_to_shared(p);
    asm volatile("ldmatrix.sync.aligned.m8n8.x4.shared.b16 {%0,%1,%2,%3}, [%4];\n"
                 : "=r"(r[0]), "=r"(r[1]), "=r"(r[2]), "=r"(r[3]) : "r"(sa));
}

__device__ __forceinline__ float sigm(float x) {
    return 1.0f / (1.0f + __expf(-x));
}
__device__ __forceinline__ float tanh_fast(float x) {
    return 2.0f / (1.0f + __expf(-2.0f * x)) - 1.0f;
}

__device__ __forceinline__ void cp16(void* s, const void* g) {
    unsigned sa = (unsigned)__cvta_generic_to_shared(s);
    asm volatile("cp.async.cg.shared.global [%0], [%1], 16;\n" :: "r"(sa), "l"(g));
}
__device__ __forceinline__ void cp_commit() { asm volatile("cp.async.commit_group;\n"); }
__device__ __forceinline__ void cp_wait0()  { asm volatile("cp.async.wait_group 0;\n"); }

// Grid barrier: release-add + acquire-poll.
__device__ __forceinline__ void gridbar(unsigned int* ctr, unsigned int target) {
    __syncthreads();
    if (threadIdx.x == 0) {
        asm volatile("red.release.gpu.global.add.u32 [%0], 1;\n" :: "l"(ctr) : "memory");
        unsigned int v;
        do {
            asm volatile("ld.acquire.gpu.global.u32 %0, [%1];\n" : "=r"(v) : "l"(ctr) : "memory");
        } while (v < target);
    }
    __syncthreads();
}

// ---------------- prep ----------------
__global__ void prep_kernel(const float* __restrict__ x,
                            const float* __restrict__ wih1, const float* __restrict__ whh1,
                            const float* __restrict__ wih2, const float* __restrict__ whh2) {
    long idx = (long)blockIdx.x * blockDim.x + threadIdx.x;
    long stride = (long)gridDim.x * blockDim.x;
    if (idx == 0) { d_bar1[0] = 0u; d_bar1[1] = 0u; d_bar2[0] = 0u; d_bar2[1] = 0u; }
    for (long i = idx; i < 16384L * 1024L; i += stride) d_xh[i]   = __float2half(x[i]);
    for (long i = idx; i < 1536L * 1024L;  i += stride) d_wih1[i] = __float2half(wih1[i]);
    for (long i = idx; i < 1536L * 512L;   i += stride) d_whh1[i] = __float2half(whh1[i]);
    for (long i = idx; i < 3072L * 512L;   i += stride) d_wih2[i] = __float2half(wih2[i]);
    for (long i = idx; i < 3072L * 1024L;  i += stride) d_whh2[i] = __float2half(whh2[i]);
}

// ---------------- pipelined SMEM GEMM (unchanged) ----------------
#define SSTR 40
__global__ __launch_bounds__(256) void gemm_tn_kernel(
        const __half* __restrict__ A, const __half* __restrict__ W,
        const float* __restrict__ bias, float* __restrict__ C,
        int M, int N, int K) {
    __shared__ __half sA[2][128 * SSTR];
    __shared__ __half sB[2][128 * SSTR];

    const int bn = blockIdx.x * 128;
    const int bm = blockIdx.y * 128;
    const int tid = threadIdx.x;
    const int w = tid >> 5, lane = tid & 31;
    const int g = lane >> 2, tg = lane & 3;
    const int wm = (w >> 2) * 64;
    const int wn = (w & 3) * 32;

    float acc[4][4][4];
#pragma unroll
    for (int mt = 0; mt < 4; mt++)
#pragma unroll
        for (int nt = 0; nt < 4; nt++)
#pragma unroll
            for (int e = 0; e < 4; e++) acc[mt][nt][e] = 0.0f;

    const int KT = K >> 5;
    {
#pragma unroll
        for (int c = 0; c < 2; c++) {
            int chunk = tid + c * 256;
            int r = chunk >> 2, cc = chunk & 3;
            cp16(&sA[0][r * SSTR + cc * 8], A + (long)(bm + r) * K + cc * 8);
            cp16(&sB[0][r * SSTR + cc * 8], W + (long)(bn + r) * K + cc * 8);
        }
        cp_commit();
    }

    for (int kt = 0; kt < KT; kt++) {
        cp_wait0();
        __syncthreads();
        if (kt + 1 < KT) {
            int k0 = (kt + 1) << 5;
            int nb = (kt + 1) & 1;
#pragma unroll
            for (int c = 0; c < 2; c++) {
                int chunk = tid + c * 256;
                int r = chunk >> 2, cc = chunk & 3;
                cp16(&sA[nb][r * SSTR + cc * 8], A + (long)(bm + r) * K + k0 + cc * 8);
                cp16(&sB[nb][r * SSTR + cc * 8], W + (long)(bn + r) * K + k0 + cc * 8);
            }
            cp_commit();
        }
        const __half* a_s = sA[kt & 1];
        const __half* b_s = sB[kt & 1];
#pragma unroll
        for (int ks = 0; ks < 2; ks++) {
            const int kk = ks * 16;
            uint32_t af[4][4];
#pragma unroll
            for (int mt = 0; mt < 4; mt++) {
                int r = wm + mt * 16 + g;
                af[mt][0] = ld32h(a_s + r * SSTR + kk + tg * 2);
                af[mt][1] = ld32h(a_s + (r + 8) * SSTR + kk + tg * 2);
                af[mt][2] = ld32h(a_s + r * SSTR + kk + tg * 2 + 8);
                af[mt][3] = ld32h(a_s + (r + 8) * SSTR + kk + tg * 2 + 8);
            }
            uint32_t bf[4][2];
#pragma unroll
            for (int nt = 0; nt < 4; nt++) {
                int n = wn + nt * 8 + g;
                bf[nt][0] = ld32h(b_s + n * SSTR + kk + tg * 2);
                bf[nt][1] = ld32h(b_s + n * SSTR + kk + tg * 2 + 8);
            }
#pragma unroll
            for (int mt = 0; mt < 4; mt++)
#pragma unroll
                for (int nt = 0; nt < 4; nt++) mma16816(acc[mt][nt], af[mt], bf[nt]);
        }
    }

#pragma unroll
    for (int mt = 0; mt < 4; mt++) {
        int row0 = bm + wm + mt * 16 + g;
#pragma unroll
        for (int nt = 0; nt < 4; nt++) {
            int col = bn + wn + nt * 8 + tg * 2;
            float b0 = bias[col], b1 = bias[col + 1];
            float2 v0 = make_float2(acc[mt][nt][0] + b0, acc[mt][nt][1] + b1);
            float2 v1 = make_float2(acc[mt][nt][2] + b0, acc[mt][nt][3] + b1);
            *reinterpret_cast<float2*>(&C[(long)row0 * N + col])       = v0;
            *reinterpret_cast<float2*>(&C[(long)(row0 + 8) * N + col]) = v1;
        }
    }
}

// ---------------- persistent GRU recurrence (batch-split groups) ----------------
// 2 independent batch-groups of 32 rows, each with CJ column-CTAs (16 j-cols per CTA)
// and its OWN barrier. Per step: stage [32 x H] h tile (cp.async), ldmatrix a-frags,
// LDS.64 b-frags from SMEM-resident W_hh, 4-way K reduction, register h_prev,
// gx[t+1] prefetched before the barrier.
template <int H, int LAYER>
__global__ __launch_bounds__(256) void rec_kernel(
        const float* __restrict__ gx, const __half* __restrict__ whh,
        const float* __restrict__ bhh, float* __restrict__ outp,
        unsigned int* __restrict__ barctr) {
    constexpr int K = H;
    constexpr int Kw = K / 4;                   // per-K-chunk width
    constexpr int KI = Kw / 16;                 // mma k-iters per warp
    constexpr int CJ = H / 16;                  // column CTAs per group (32 / 64)
    constexpr int GA = 3 * H;
    constexpr int STRIDE = H + 8;
    constexpr int CH_ROW = H / 8;
    constexpr int LOG_CH = (H == 512) ? 6 : 7;

    extern __shared__ unsigned char smem[];
    __half*   sH   = reinterpret_cast<__half*>(smem);                              // [32][STRIDE]
    uint32_t* sB   = reinterpret_cast<uint32_t*>(smem + (size_t)32 * STRIDE * 2);  // [4*KI*6][32][2]
    float*    sRed = reinterpret_cast<float*>(smem + (size_t)32 * STRIDE * 2 + (size_t)4 * KI * 6 * 64 * 4); // [4][32][48]

    const int tid = threadIdx.x;
    const int w = tid >> 5, lane = tid & 31;
    const int km = w & 3, mh = w >> 2;          // K-chunk, M-half (16 rows each)
    const int g = lane >> 2, tg = lane & 3;
    const int grp = blockIdx.x & 1;             // batch group (rows grp*32..+31)
    const int j0 = (blockIdx.x >> 1) * 16;      // 16 j-columns per CTA
    const int row0 = grp * 32;
    const int mrow = mh * 16;
    const int lr = lane & 15, lc = (lane >> 4) << 3;
    unsigned int* ctr = barctr + grp;

    // Stage W_hh fragments once: n-dim = 48 gate cols, 6 n-tiles of 8.
    if (mh == 0) {
#pragma unroll
        for (int i = 0; i < KI; i++) {
            int k0 = km * Kw + i * 16;
#pragma unroll
            for (int nt = 0; nt < 6; nt++) {
                int gate = nt >> 1;
                int jl = (nt & 1) * 8 + g;
                int n = gate * H + j0 + jl;
                const __half* p = whh + (long)n * K + k0 + tg * 2;
                int base2 = ((((km * KI + i) * 6 + nt) * 32) + lane) * 2;
                sB[base2]     = ld32h(p);
                sB[base2 + 1] = ld32h(p + 8);
            }
        }
    }

    // Per-thread gate state: 2 values; idx = tid + v*256 over 32 rows x 16 cols.
    float hp[2] = {0.0f, 0.0f};
    float br[2], bz[2], bn_[2];
    int   bloc[2], jidx[2];
    const float* gxbase[2];
#pragma unroll
    for (int v = 0; v < 2; v++) {
        int idx = tid + v * 256;
        int b = idx >> 4, jl = idx & 15, j = j0 + jl;
        bloc[v] = b; jidx[v] = j;
        br[v]  = bhh[j];
        bz[v]  = bhh[H + j];
        bn_[v] = bhh[2 * H + j];
        gxbase[v] = gx + (long)(row0 + b) * TT * GA + j;
        d_hbuf16[0][(row0 + b) * H + j] = __float2half(0.0f);
    }

    // Prefetch gx for t=0 (flies during the initial barrier).
    float xr[2], xz[2], xn[2];
#pragma unroll
    for (int v = 0; v < 2; v++) {
        const float* p = gxbase[v];
        xr[v] = __ldg(p);
        xz[v] = __ldg(p + H);
        xn[v] = __ldg(p + 2 * H);
    }

    unsigned int ibar = 0;
    gridbar(ctr, (++ibar) * CJ);

    for (int t = 0; t < TT; t++) {
        const int cur = t & 1, nxt = cur ^ 1;
        const __half* hA = d_hbuf16[cur] + (long)row0 * H;

        // Stage h tile [32 x H] -> SMEM.
#pragma unroll
        for (int c = tid; c < 32 * CH_ROW; c += 256) {
            int r = c >> LOG_CH, cc = c & (CH_ROW - 1);
            cp16(&sH[r * STRIDE + cc * 8], hA + (long)r * H + cc * 8);
        }
        cp_commit();
        cp_wait0();
        __syncthreads();

        float acc[6][4];
#pragma unroll
        for (int q = 0; q < 6; q++)
#pragma unroll
            for (int e = 0; e < 4; e++) acc[q][e] = 0.0f;

#pragma unroll
        for (int i = 0; i < KI; i++) {
            int k0 = km * Kw + i * 16;
            uint32_t a[4];
            ldsm_x4(a, sH + (mrow + lr) * STRIDE + k0 + lc);
#pragma unroll
            for (int nt = 0; nt < 6; nt++) {
                int base2 = ((((km * KI + i) * 6 + nt) * 32) + lane) * 2;
                uint2 bp = *reinterpret_cast<const uint2*>(&sB[base2]);
                uint32_t b[2] = { bp.x, bp.y };
                mma16816(acc[nt], a, b);
            }
        }

        // per-K-chunk partials -> SMEM: [4][32 rows][48 cols]
#pragma unroll
        for (int nt = 0; nt < 6; nt++) {
            float* c = acc[nt];
            int col = nt * 8 + tg * 2;
            int row = mrow + g;
            *reinterpret_cast<float2*>(&sRed[(km * 32 + row) * 48 + col])     = make_float2(c[0], c[1]);
            *reinterpret_cast<float2*>(&sRed[(km * 32 + row + 8) * 48 + col]) = make_float2(c[2], c[3]);
        }
        __syncthreads();

        // gate math: 2 values per thread.
#pragma unroll
        for (int v = 0; v < 2; v++) {
            int b = bloc[v], j = jidx[v];
            int jl = j - j0;
            float hr = br[v], hz = bz[v], hn = bn_[v];
#pragma unroll
            for (int kk = 0; kk < 4; kk++) {
                const float* rr = &sRed[(kk * 32 + b) * 48];
                hr += rr[jl];
                hz += rr[16 + jl];
                hn += rr[32 + jl];
            }
            float r = sigm(xr[v] + hr);
            float z = sigm(xz[v] + hz);
            float n = tanh_fast(fmaf(r, hn, xn[v]));
            float hnew = fmaf(z, hp[v] - n, n);
            hp[v] = hnew;
            d_hbuf16[nxt][(row0 + b) * H + j] = __float2half(hnew);
            if (LAYER == 1) {
                d_h1seq[((long)(row0 + b) * TT + t) * H + j] = __float2half(fmaxf(hnew, 0.0f));
            } else {
                outp[((long)(row0 + b) * TT + t) * H + j] = hnew;
            }
        }

        // Prefetch gx for t+1 BEFORE the barrier (loads fly during the wait).
        if (t + 1 < TT) {
#pragma unroll
            for (int v = 0; v < 2; v++) {
                const float* p = gxbase[v] + (long)(t + 1) * GA;
                xr[v] = __ldg(p);
                xz[v] = __ldg(p + H);
                xn[v] = __ldg(p + 2 * H);
            }
        }
        gridbar(ctr, (++ibar) * CJ);
    }
}

// ---------------- launch ----------------
extern "C" void kernel_launch(void* const* d_in, const int* in_sizes, int n_in,
                              void* d_out, int out_size) {
    const float* x    = (const float*)d_in[0];
    const float* wih1 = (const float*)d_in[1];
    const float* whh1 = (const float*)d_in[2];
    const float* bih1 = (const float*)d_in[3];
    const float* bhh1 = (const float*)d_in[4];
    const float* wih2 = (const float*)d_in[5];
    const float* whh2 = (const float*)d_in[6];
    const float* bih2 = (const float*)d_in[7];
    const float* bhh2 = (const float*)d_in[8];
    float* out = (float*)d_out;

    void *p_xh, *p_wih1, *p_whh1, *p_wih2, *p_whh2, *p_gx1, *p_gx2, *p_h1, *p_bar1, *p_bar2;
    cudaGetSymbolAddress(&p_xh, d_xh);
    cudaGetSymbolAddress(&p_wih1, d_wih1);
    cudaGetSymbolAddress(&p_whh1, d_whh1);
    cudaGetSymbolAddress(&p_wih2, d_wih2);
    cudaGetSymbolAddress(&p_whh2, d_whh2);
    cudaGetSymbolAddress(&p_gx1, d_gx1);
    cudaGetSymbolAddress(&p_gx2, d_gx2);
    cudaGetSymbolAddress(&p_h1, d_h1seq);
    cudaGetSymbolAddress(&p_bar1, d_bar1);
    cudaGetSymbolAddress(&p_bar2, d_bar2);

    // smem: sH(32*STRIDE*2) + sB(4*KI*6*64*4) + sRed(4*32*48*4 = 24576)
    const int SMEM1 = 32 * (512 + 8) * 2  + 4 * 8  * 6 * 64 * 4 + 24576;  // 33280+49152+24576 = 107008
    const int SMEM2 = 32 * (1024 + 8) * 2 + 4 * 16 * 6 * 64 * 4 + 24576;  // 66048+98304+24576 = 188928
    cudaFuncSetAttribute(rec_kernel<512, 1>,  cudaFuncAttributeMaxDynamicSharedMemorySize, SMEM1);
    cudaFuncSetAttribute(rec_kernel<1024, 2>, cudaFuncAttributeMaxDynamicSharedMemorySize, SMEM2);

    prep_kernel<<<2048, 256>>>(x, wih1, whh1, wih2, whh2);

    {   // gx1 = x @ W_ih1^T + b_ih1 : [16384,1536], K=1024
        dim3 grid(1536 / 128, 16384 / 128);
        gemm_tn_kernel<<<grid, 256>>>((const __half*)p_xh, (const __half*)p_wih1,
                                      bih1, (float*)p_gx1, 16384, 1536, 1024);
    }

    // layer-1 recurrence: 2 groups x 32 column-CTAs = 64 CTAs
    rec_kernel<512, 1><<<64, 256, SMEM1>>>((const float*)p_gx1, (const __half*)p_whh1,
                                           bhh1, nullptr, (unsigned int*)p_bar1);

    {   // gx2 = relu(h1) @ W_ih2^T + b_ih2 : [16384,3072], K=512
        dim3 grid(3072 / 128, 16384 / 128);
        gemm_tn_kernel<<<grid, 256>>>((const __half*)p_h1, (const __half*)p_wih2,
                                      bih2, (float*)p_gx2, 16384, 3072, 512);
    }

    // layer-2 recurrence: 2 groups x 64 column-CTAs = 128 CTAs
    rec_kernel<1024, 2><<<128, 256, SMEM2>>>((const float*)p_gx2, (const __half*)p_whh2,
                                             bhh2, out, (unsigned int*)p_bar2);
}

// round 6
// speedup vs baseline: 2.1643x; 1.1066x over previous
#include <cuda_runtime.h>
#include <cuda_fp16.h>
#include <math.h>
#include <stdint.h>

#define BB 64
#define TT 256
#define IIN 1024
#define HHID 512

// ---------------- device scratch (static: no allocations allowed) ----------------
__device__ __half d_xh[16384u * 1024u];
__device__ __half d_wih1[1536u * 1024u];
__device__ __half d_whh1[1536u * 512u];
__device__ __half d_wih2[3072u * 512u];
__device__ __half d_whh2[3072u * 1024u];
__device__ float  d_gx1[16384u * 1536u];
__device__ float  d_gx2[16384u * 3072u];
__device__ __half d_h1seq[16384u * 512u];
__device__ __half d_hbuf16[2][64 * 1024];
__device__ unsigned int d_bar1[4];
__device__ unsigned int d_bar2[2];

// ---------------- helpers ----------------
__device__ __forceinline__ uint32_t ld32h(const __half* p) {
    return *reinterpret_cast<const uint32_t*>(p);
}

__device__ __forceinline__ void mma16816(float* c, const uint32_t* a, const uint32_t* b) {
    asm volatile(
        "mma.sync.aligned.m16n8k16.row.col.f32.f16.f16.f32 "
        "{%0,%1,%2,%3}, {%4,%5,%6,%7}, {%8,%9}, {%0,%1,%2,%3};\n"
        : "+f"(c[0]), "+f"(c[1]), "+f"(c[2]), "+f"(c[3])
        : "r"(a[0]), "r"(a[1]), "r"(a[2]), "r"(a[3]), "r"(b[0]), "r"(b[1]));
}

__device__ __forceinline__ void ldsm_x4(uint32_t* r, const __half* p) {
    unsigned sa = (unsigned)__cvta_generic_to_shared(p);
    asm volatile("ldmatrix.sync.aligned.m8n8.x4.shared.b16 {%0,%1,%2,%3}, [%4];\n"
                 : "=r"(r[0]), "=r"(r[1]), "=r"(r[2]), "=r"(r[3]) : "r"(sa));
}

__device__ __forceinline__ float sigm(float x) {
    return 1.0f / (1.0f + __expf(-x));
}
__device__ __forceinline__ float tanh_fast(float x) {
    return 2.0f / (1.0f + __expf(-2.0f * x)) - 1.0f;
}

__device__ __forceinline__ void cp16(void* s, const void* g) {
    unsigned sa = (unsigned)__cvta_generic_to_shared(s);
    asm volatile("cp.async.cg.shared.global [%0], [%1], 16;\n" :: "r"(sa), "l"(g));
}
__device__ __forceinline__ void cp_commit() { asm volatile("cp.async.commit_group;\n"); }
__device__ __forceinline__ void cp_wait0()  { asm volatile("cp.async.wait_group 0;\n"); }

// Grid barrier: release-add + acquire-poll.
__device__ __forceinline__ void gridbar(unsigned int* ctr, unsigned int target) {
    __syncthreads();
    if (threadIdx.x == 0) {
        asm volatile("red.release.gpu.global.add.u32 [%0], 1;\n" :: "l"(ctr) : "memory");
        unsigned int v;
        do {
            asm volatile("ld.acquire.gpu.global.u32 %0, [%1];\n" : "=r"(v) : "l"(ctr) : "memory");
        } while (v < target);
    }
    __syncthreads();
}

// ---------------- prep ----------------
__global__ void prep_kernel(const float* __restrict__ x,
                            const float* __restrict__ wih1, const float* __restrict__ whh1,
                            const float* __restrict__ wih2, const float* __restrict__ whh2) {
    long idx = (long)blockIdx.x * blockDim.x + threadIdx.x;
    long stride = (long)gridDim.x * blockDim.x;
    if (idx == 0) {
        d_bar1[0] = d_bar1[1] = d_bar1[2] = d_bar1[3] = 0u;
        d_bar2[0] = d_bar2[1] = 0u;
    }
    for (long i = idx; i < 16384L * 1024L; i += stride) d_xh[i]   = __float2half(x[i]);
    for (long i = idx; i < 1536L * 1024L;  i += stride) d_wih1[i] = __float2half(wih1[i]);
    for (long i = idx; i < 1536L * 512L;   i += stride) d_whh1[i] = __float2half(whh1[i]);
    for (long i = idx; i < 3072L * 512L;   i += stride) d_wih2[i] = __float2half(wih2[i]);
    for (long i = idx; i < 3072L * 1024L;  i += stride) d_whh2[i] = __float2half(whh2[i]);
}

// ---------------- pipelined SMEM GEMM (unchanged, known-good) ----------------
#define SSTR 40
__global__ __launch_bounds__(256) void gemm_tn_kernel(
        const __half* __restrict__ A, const __half* __restrict__ W,
        const float* __restrict__ bias, float* __restrict__ C,
        int M, int N, int K) {
    __shared__ __half sA[2][128 * SSTR];
    __shared__ __half sB[2][128 * SSTR];

    const int bn = blockIdx.x * 128;
    const int bm = blockIdx.y * 128;
    const int tid = threadIdx.x;
    const int w = tid >> 5, lane = tid & 31;
    const int g = lane >> 2, tg = lane & 3;
    const int wm = (w >> 2) * 64;
    const int wn = (w & 3) * 32;

    float acc[4][4][4];
#pragma unroll
    for (int mt = 0; mt < 4; mt++)
#pragma unroll
        for (int nt = 0; nt < 4; nt++)
#pragma unroll
            for (int e = 0; e < 4; e++) acc[mt][nt][e] = 0.0f;

    const int KT = K >> 5;
    {
#pragma unroll
        for (int c = 0; c < 2; c++) {
            int chunk = tid + c * 256;
            int r = chunk >> 2, cc = chunk & 3;
            cp16(&sA[0][r * SSTR + cc * 8], A + (long)(bm + r) * K + cc * 8);
            cp16(&sB[0][r * SSTR + cc * 8], W + (long)(bn + r) * K + cc * 8);
        }
        cp_commit();
    }

    for (int kt = 0; kt < KT; kt++) {
        cp_wait0();
        __syncthreads();
        if (kt + 1 < KT) {
            int k0 = (kt + 1) << 5;
            int nb = (kt + 1) & 1;
#pragma unroll
            for (int c = 0; c < 2; c++) {
                int chunk = tid + c * 256;
                int r = chunk >> 2, cc = chunk & 3;
                cp16(&sA[nb][r * SSTR + cc * 8], A + (long)(bm + r) * K + k0 + cc * 8);
                cp16(&sB[nb][r * SSTR + cc * 8], W + (long)(bn + r) * K + k0 + cc * 8);
            }
            cp_commit();
        }
        const __half* a_s = sA[kt & 1];
        const __half* b_s = sB[kt & 1];
#pragma unroll
        for (int ks = 0; ks < 2; ks++) {
            const int kk = ks * 16;
            uint32_t af[4][4];
#pragma unroll
            for (int mt = 0; mt < 4; mt++) {
                int r = wm + mt * 16 + g;
                af[mt][0] = ld32h(a_s + r * SSTR + kk + tg * 2);
                af[mt][1] = ld32h(a_s + (r + 8) * SSTR + kk + tg * 2);
                af[mt][2] = ld32h(a_s + r * SSTR + kk + tg * 2 + 8);
                af[mt][3] = ld32h(a_s + (r + 8) * SSTR + kk + tg * 2 + 8);
            }
            uint32_t bf[4][2];
#pragma unroll
            for (int nt = 0; nt < 4; nt++) {
                int n = wn + nt * 8 + g;
                bf[nt][0] = ld32h(b_s + n * SSTR + kk + tg * 2);
                bf[nt][1] = ld32h(b_s + n * SSTR + kk + tg * 2 + 8);
            }
#pragma unroll
            for (int mt = 0; mt < 4; mt++)
#pragma unroll
                for (int nt = 0; nt < 4; nt++) mma16816(acc[mt][nt], af[mt], bf[nt]);
        }
    }

#pragma unroll
    for (int mt = 0; mt < 4; mt++) {
        int row0 = bm + wm + mt * 16 + g;
#pragma unroll
        for (int nt = 0; nt < 4; nt++) {
            int col = bn + wn + nt * 8 + tg * 2;
            float b0 = bias[col], b1 = bias[col + 1];
            float2 v0 = make_float2(acc[mt][nt][0] + b0, acc[mt][nt][1] + b1);
            float2 v1 = make_float2(acc[mt][nt][2] + b0, acc[mt][nt][3] + b1);
            *reinterpret_cast<float2*>(&C[(long)row0 * N + col])       = v0;
            *reinterpret_cast<float2*>(&C[(long)(row0 + 8) * N + col]) = v1;
        }
    }
}

// ---------------- persistent GRU recurrence ----------------
// GROUPS independent batch-groups of ROWS rows; CJ = H/16 column-CTAs per group.
// 8 warps = KSPLIT K-chunks x (ROWS/16) M-halves. Each warp SELF-STAGES its own
// 16 rows x own K-chunk via cp.async (waits only its own group, __syncwarp), so
// MMA starts without a CTA-wide stage barrier. KSPLIT-way SMEM reduce, register
// h_prev, gx[t+1] prefetched before the single grid barrier per step.
template <int H, int LAYER, int ROWS, int KSPLIT, int GROUPS>
__global__ __launch_bounds__(256) void rec_kernel(
        const float* __restrict__ gx, const __half* __restrict__ whh,
        const float* __restrict__ bhh, float* __restrict__ outp,
        unsigned int* __restrict__ barctr) {
    constexpr int K = H;
    constexpr int Kw = K / KSPLIT;
    constexpr int KI = Kw / 16;
    constexpr int CJ = H / 16;
    constexpr int GA = 3 * H;
    constexpr int STRIDE = H + 8;
    constexpr int VAL = (ROWS * 16) / 256;      // gate values per thread (1 or 2)

    extern __shared__ unsigned char smem[];
    __half*   sH   = reinterpret_cast<__half*>(smem);                                // [ROWS][STRIDE]
    uint32_t* sB   = reinterpret_cast<uint32_t*>(smem + (size_t)ROWS * STRIDE * 2);  // [KSPLIT*KI*6][32][2]
    float*    sRed = reinterpret_cast<float*>(smem + (size_t)ROWS * STRIDE * 2 + (size_t)KSPLIT * KI * 6 * 64 * 4); // [KSPLIT][ROWS][48]

    const int tid = threadIdx.x;
    const int w = tid >> 5, lane = tid & 31;
    const int km = w % KSPLIT, mh = w / KSPLIT;
    const int g = lane >> 2, tg = lane & 3;
    const int grp = blockIdx.x % GROUPS;
    const int j0 = (blockIdx.x / GROUPS) * 16;
    const int row0 = grp * ROWS;
    const int mrow = mh * 16;
    const int lr = lane & 15, lc = (lane >> 4) << 3;
    unsigned int* ctr = barctr + grp;

    // Stage W_hh fragments once: 48 gate cols = 6 n-tiles of 8.
    if (mh == 0) {
#pragma unroll
        for (int i = 0; i < KI; i++) {
            int k0 = km * Kw + i * 16;
#pragma unroll
            for (int nt = 0; nt < 6; nt++) {
                int gate = nt >> 1;
                int jl = (nt & 1) * 8 + g;
                int n = gate * H + j0 + jl;
                const __half* p = whh + (long)n * K + k0 + tg * 2;
                int base2 = ((((km * KI + i) * 6 + nt) * 32) + lane) * 2;
                sB[base2]     = ld32h(p);
                sB[base2 + 1] = ld32h(p + 8);
            }
        }
    }

    // Per-thread gate state.
    float hp[VAL];
    float br[VAL], bz[VAL], bn_[VAL];
    int   bloc[VAL], jidx[VAL];
    const float* gxbase[VAL];
#pragma unroll
    for (int v = 0; v < VAL; v++) {
        int idx = tid + v * 256;
        int b = idx >> 4, jl = idx & 15, j = j0 + jl;
        hp[v] = 0.0f;
        bloc[v] = b; jidx[v] = j;
        br[v]  = bhh[j];
        bz[v]  = bhh[H + j];
        bn_[v] = bhh[2 * H + j];
        gxbase[v] = gx + (long)(row0 + b) * TT * GA + j;
        d_hbuf16[0][(row0 + b) * H + j] = __float2half(0.0f);
    }

    // Prefetch gx for t=0.
    float xr[VAL], xz[VAL], xn[VAL];
#pragma unroll
    for (int v = 0; v < VAL; v++) {
        const float* p = gxbase[v];
        xr[v] = __ldg(p);
        xz[v] = __ldg(p + H);
        xn[v] = __ldg(p + 2 * H);
    }

    unsigned int ibar = 0;
    gridbar(ctr, (++ibar) * CJ);

    for (int t = 0; t < TT; t++) {
        const int cur = t & 1, nxt = cur ^ 1;
        const __half* hA = d_hbuf16[cur] + (long)row0 * H;

        // Self-stage: this warp's 16 rows x its K-chunk (16B granules).
        constexpr int CHUNKS = 16 * Kw / 8;     // 16B chunks per warp
#pragma unroll
        for (int c = 0; c < CHUNKS / 32; c++) {
            int idx = c * 32 + lane;
            int r = idx / (Kw / 8), cc = idx % (Kw / 8);
            int row = mrow + r, col = km * Kw + cc * 8;
            cp16(&sH[row * STRIDE + col], hA + (long)row * H + col);
        }
        cp_commit();
        cp_wait0();
        __syncwarp(0xffffffffu);

        float acc[6][4];
#pragma unroll
        for (int q = 0; q < 6; q++)
#pragma unroll
            for (int e = 0; e < 4; e++) acc[q][e] = 0.0f;

#pragma unroll
        for (int i = 0; i < KI; i++) {
            int k0 = km * Kw + i * 16;
            uint32_t a[4];
            ldsm_x4(a, sH + (mrow + lr) * STRIDE + k0 + lc);
#pragma unroll
            for (int nt = 0; nt < 6; nt++) {
                int base2 = ((((km * KI + i) * 6 + nt) * 32) + lane) * 2;
                uint2 bp = *reinterpret_cast<const uint2*>(&sB[base2]);
                uint32_t b[2] = { bp.x, bp.y };
                mma16816(acc[nt], a, b);
            }
        }

        // per-K-chunk partials -> SMEM: [KSPLIT][ROWS][48]
#pragma unroll
        for (int nt = 0; nt < 6; nt++) {
            float* c = acc[nt];
            int col = nt * 8 + tg * 2;
            int row = mrow + g;
            *reinterpret_cast<float2*>(&sRed[(km * ROWS + row) * 48 + col])     = make_float2(c[0], c[1]);
            *reinterpret_cast<float2*>(&sRed[(km * ROWS + row + 8) * 48 + col]) = make_float2(c[2], c[3]);
        }
        __syncthreads();

        // gate math.
#pragma unroll
        for (int v = 0; v < VAL; v++) {
            int b = bloc[v], j = jidx[v];
            int jl = j - j0;
            float hr = br[v], hz = bz[v], hn = bn_[v];
#pragma unroll
            for (int kk = 0; kk < KSPLIT; kk++) {
                const float* rr = &sRed[(kk * ROWS + b) * 48];
                hr += rr[jl];
                hz += rr[16 + jl];
                hn += rr[32 + jl];
            }
            float r = sigm(xr[v] + hr);
            float z = sigm(xz[v] + hz);
            float n = tanh_fast(fmaf(r, hn, xn[v]));
            float hnew = fmaf(z, hp[v] - n, n);
            hp[v] = hnew;
            d_hbuf16[nxt][(row0 + b) * H + j] = __float2half(hnew);
            if (LAYER == 1) {
                d_h1seq[((long)(row0 + b) * TT + t) * H + j] = __float2half(fmaxf(hnew, 0.0f));
            } else {
                outp[((long)(row0 + b) * TT + t) * H + j] = hnew;
            }
        }

        // Prefetch gx for t+1 BEFORE the barrier.
        if (t + 1 < TT) {
#pragma unroll
            for (int v = 0; v < VAL; v++) {
                const float* p = gxbase[v] + (long)(t + 1) * GA;
                xr[v] = __ldg(p);
                xz[v] = __ldg(p + H);
                xn[v] = __ldg(p + 2 * H);
            }
        }
        gridbar(ctr, (++ibar) * CJ);
    }
}

// ---------------- launch ----------------
extern "C" void kernel_launch(void* const* d_in, const int* in_sizes, int n_in,
                              void* d_out, int out_size) {
    const float* x    = (const float*)d_in[0];
    const float* wih1 = (const float*)d_in[1];
    const float* whh1 = (const float*)d_in[2];
    const float* bih1 = (const float*)d_in[3];
    const float* bhh1 = (const float*)d_in[4];
    const float* wih2 = (const float*)d_in[5];
    const float* whh2 = (const float*)d_in[6];
    const float* bih2 = (const float*)d_in[7];
    const float* bhh2 = (const float*)d_in[8];
    float* out = (float*)d_out;

    void *p_xh, *p_wih1, *p_whh1, *p_wih2, *p_whh2, *p_gx1, *p_gx2, *p_h1, *p_bar1, *p_bar2;
    cudaGetSymbolAddress(&p_xh, d_xh);
    cudaGetSymbolAddress(&p_wih1, d_wih1);
    cudaGetSymbolAddress(&p_whh1, d_whh1);
    cudaGetSymbolAddress(&p_wih2, d_wih2);
    cudaGetSymbolAddress(&p_whh2, d_whh2);
    cudaGetSymbolAddress(&p_gx1, d_gx1);
    cudaGetSymbolAddress(&p_gx2, d_gx2);
    cudaGetSymbolAddress(&p_h1, d_h1seq);
    cudaGetSymbolAddress(&p_bar1, d_bar1);
    cudaGetSymbolAddress(&p_bar2, d_bar2);

    // layer1: ROWS=16, KSPLIT=8, GROUPS=4
    //   sH 16*520*2=16640, sB 8*4*6*64*4=49152, sRed 8*16*48*4=24576 -> 90368
    const int SMEM1 = 16 * (512 + 8) * 2 + 8 * 4 * 6 * 64 * 4 + 8 * 16 * 48 * 4;
    // layer2: ROWS=32, KSPLIT=4, GROUPS=2
    //   sH 32*1032*2=66048, sB 4*16*6*64*4=98304, sRed 4*32*48*4=24576 -> 188928
    const int SMEM2 = 32 * (1024 + 8) * 2 + 4 * 16 * 6 * 64 * 4 + 4 * 32 * 48 * 4;
    cudaFuncSetAttribute((const void*)rec_kernel<512, 1, 16, 8, 4>,
                         cudaFuncAttributeMaxDynamicSharedMemorySize, SMEM1);
    cudaFuncSetAttribute((const void*)rec_kernel<1024, 2, 32, 4, 2>,
                         cudaFuncAttributeMaxDynamicSharedMemorySize, SMEM2);

    prep_kernel<<<2048, 256>>>(x, wih1, whh1, wih2, whh2);

    {   // gx1 = x @ W_ih1^T + b_ih1 : [16384,1536], K=1024
        dim3 grid(1536 / 128, 16384 / 128);
        gemm_tn_kernel<<<grid, 256>>>((const __half*)p_xh, (const __half*)p_wih1,
                                      bih1, (float*)p_gx1, 16384, 1536, 1024);
    }

    // layer-1 recurrence: 4 groups x 32 column-CTAs = 128 CTAs
    rec_kernel<512, 1, 16, 8, 4><<<128, 256, SMEM1>>>(
        (const float*)p_gx1, (const __half*)p_whh1, bhh1, nullptr, (unsigned int*)p_bar1);

    {   // gx2 = relu(h1) @ W_ih2^T + b_ih2 : [16384,3072], K=512
        dim3 grid(3072 / 128, 16384 / 128);
        gemm_tn_kernel<<<grid, 256>>>((const __half*)p_h1, (const __half*)p_wih2,
                                      bih2, (float*)p_gx2, 16384, 3072, 512);
    }

    // layer-2 recurrence: 2 groups x 64 column-CTAs = 128 CTAs
    rec_kernel<1024, 2, 32, 4, 2><<<128, 256, SMEM2>>>(
        (const float*)p_gx2, (const __half*)p_whh2, bhh2, out, (unsigned int*)p_bar2);
}

// round 7
// speedup vs baseline: 2.2425x; 1.0361x over previous
#include <cuda_runtime.h>
#include <cuda_fp16.h>
#include <math.h>
#include <stdint.h>

#define BB 64
#define TT 256
#define IIN 1024
#define HHID 512

// ---------------- device scratch (static: no allocations allowed) ----------------
__device__ __half d_xh[16384u * 1024u];
__device__ __half d_wih1[1536u * 1024u];
__device__ __half d_whh1[1536u * 512u];
__device__ __half d_wih2[3072u * 512u];
__device__ __half d_whh2[3072u * 1024u];
__device__ float  d_gx1[16384u * 1536u];
__device__ float  d_gx2[16384u * 3072u];
__device__ __half d_h1seq[16384u * 512u];
__device__ __half d_hbuf16[2][64 * 1024];
__device__ unsigned int d_bar1[4];
__device__ unsigned int d_bar2[2];

// ---------------- helpers ----------------
__device__ __forceinline__ uint32_t ld32h(const __half* p) {
    return *reinterpret_cast<const uint32_t*>(p);
}

__device__ __forceinline__ void mma16816(float* c, const uint32_t* a, const uint32_t* b) {
    asm volatile(
        "mma.sync.aligned.m16n8k16.row.col.f32.f16.f16.f32 "
        "{%0,%1,%2,%3}, {%4,%5,%6,%7}, {%8,%9}, {%0,%1,%2,%3};\n"
        : "+f"(c[0]), "+f"(c[1]), "+f"(c[2]), "+f"(c[3])
        : "r"(a[0]), "r"(a[1]), "r"(a[2]), "r"(a[3]), "r"(b[0]), "r"(b[1]));
}

__device__ __forceinline__ void ldsm_x4(uint32_t* r, const __half* p) {
    unsigned sa = (unsigned)__cvta_generic_to_shared(p);
    asm volatile("ldmatrix.sync.aligned.m8n8.x4.shared.b16 {%0,%1,%2,%3}, [%4];\n"
                 : "=r"(r[0]), "=r"(r[1]), "=r"(r[2]), "=r"(r[3]) : "r"(sa));
}

__device__ __forceinline__ float sigm(float x) {
    return 1.0f / (1.0f + __expf(-x));
}
__device__ __forceinline__ float tanh_fast(float x) {
    return 2.0f / (1.0f + __expf(-2.0f * x)) - 1.0f;
}

__device__ __forceinline__ void cp16(void* s, const void* g) {
    unsigned sa = (unsigned)__cvta_generic_to_shared(s);
    asm volatile("cp.async.cg.shared.global [%0], [%1], 16;\n" :: "r"(sa), "l"(g));
}
__device__ __forceinline__ void cp_commit() { asm volatile("cp.async.commit_group;\n"); }
__device__ __forceinline__ void cp_wait0()  { asm volatile("cp.async.wait_group 0;\n"); }
__device__ __forceinline__ void cp_wait1()  { asm volatile("cp.async.wait_group 1;\n"); }

// Grid barrier: release-add + acquire-poll.
__device__ __forceinline__ void gridbar(unsigned int* ctr, unsigned int target) {
    __syncthreads();
    if (threadIdx.x == 0) {
        asm volatile("red.release.gpu.global.add.u32 [%0], 1;\n" :: "l"(ctr) : "memory");
        unsigned int v;
        do {
            asm volatile("ld.acquire.gpu.global.u32 %0, [%1];\n" : "=r"(v) : "l"(ctr) : "memory");
        } while (v < target);
    }
    __syncthreads();
}

// ---------------- prep ----------------
__global__ void prep_kernel(const float* __restrict__ x,
                            const float* __restrict__ wih1, const float* __restrict__ whh1,
                            const float* __restrict__ wih2, const float* __restrict__ whh2) {
    long idx = (long)blockIdx.x * blockDim.x + threadIdx.x;
    long stride = (long)gridDim.x * blockDim.x;
    if (idx == 0) {
        d_bar1[0] = d_bar1[1] = d_bar1[2] = d_bar1[3] = 0u;
        d_bar2[0] = d_bar2[1] = 0u;
    }
    for (long i = idx; i < 16384L * 1024L; i += stride) d_xh[i]   = __float2half(x[i]);
    for (long i = idx; i < 1536L * 1024L;  i += stride) d_wih1[i] = __float2half(wih1[i]);
    for (long i = idx; i < 1536L * 512L;   i += stride) d_whh1[i] = __float2half(whh1[i]);
    for (long i = idx; i < 3072L * 512L;   i += stride) d_wih2[i] = __float2half(wih2[i]);
    for (long i = idx; i < 3072L * 1024L;  i += stride) d_whh2[i] = __float2half(whh2[i]);
}

// ---------------- 3-stage pipelined SMEM GEMM: C[M,N] = A[M,K] @ W[N,K]^T + bias ----------------
// CTA 128x128, K-tile 32, 3-stage cp.async (wait_group 1), padded stride 40.
#define SSTR 40
#define GSTG 3
__global__ __launch_bounds__(256) void gemm_tn_kernel(
        const __half* __restrict__ A, const __half* __restrict__ W,
        const float* __restrict__ bias, float* __restrict__ C,
        int M, int N, int K) {
    extern __shared__ __half gsm[];
    __half* sA = gsm;                    // [GSTG][128*SSTR]
    __half* sB = gsm + GSTG * 128 * SSTR;

    const int bn = blockIdx.x * 128;
    const int bm = blockIdx.y * 128;
    const int tid = threadIdx.x;
    const int w = tid >> 5, lane = tid & 31;
    const int g = lane >> 2, tg = lane & 3;
    const int wm = (w >> 2) * 64;
    const int wn = (w & 3) * 32;

    float acc[4][4][4];
#pragma unroll
    for (int mt = 0; mt < 4; mt++)
#pragma unroll
        for (int nt = 0; nt < 4; nt++)
#pragma unroll
            for (int e = 0; e < 4; e++) acc[mt][nt][e] = 0.0f;

    const int KT = K >> 5;
    // prologue: stages 0 and 1
#pragma unroll
    for (int s = 0; s < 2; s++) {
        int k0 = s << 5;
#pragma unroll
        for (int c = 0; c < 2; c++) {
            int chunk = tid + c * 256;
            int r = chunk >> 2, cc = chunk & 3;
            cp16(&sA[(s * 128 + r) * SSTR + cc * 8], A + (long)(bm + r) * K + k0 + cc * 8);
            cp16(&sB[(s * 128 + r) * SSTR + cc * 8], W + (long)(bn + r) * K + k0 + cc * 8);
        }
        cp_commit();
    }

    int sc = 0;  // compute stage index
    int sl = 2;  // next load stage index
    for (int kt = 0; kt < KT; kt++) {
        cp_wait1();           // oldest group (tile kt) has landed
        __syncthreads();      // and everyone is done computing tile kt-1's buffer
        if (kt + 2 < KT) {
            int k0 = (kt + 2) << 5;
#pragma unroll
            for (int c = 0; c < 2; c++) {
                int chunk = tid + c * 256;
                int r = chunk >> 2, cc = chunk & 3;
                cp16(&sA[(sl * 128 + r) * SSTR + cc * 8], A + (long)(bm + r) * K + k0 + cc * 8);
                cp16(&sB[(sl * 128 + r) * SSTR + cc * 8], W + (long)(bn + r) * K + k0 + cc * 8);
            }
        }
        cp_commit();          // commit (possibly empty) group to keep count in sync
        if (++sl == GSTG) sl = 0;

        const __half* a_s = sA + sc * 128 * SSTR;
        const __half* b_s = sB + sc * 128 * SSTR;
        if (++sc == GSTG) sc = 0;
#pragma unroll
        for (int ks = 0; ks < 2; ks++) {
            const int kk = ks * 16;
            uint32_t af[4][4];
#pragma unroll
            for (int mt = 0; mt < 4; mt++) {
                int r = wm + mt * 16 + g;
                af[mt][0] = ld32h(a_s + r * SSTR + kk + tg * 2);
                af[mt][1] = ld32h(a_s + (r + 8) * SSTR + kk + tg * 2);
                af[mt][2] = ld32h(a_s + r * SSTR + kk + tg * 2 + 8);
                af[mt][3] = ld32h(a_s + (r + 8) * SSTR + kk + tg * 2 + 8);
            }
            uint32_t bf[4][2];
#pragma unroll
            for (int nt = 0; nt < 4; nt++) {
                int n = wn + nt * 8 + g;
                bf[nt][0] = ld32h(b_s + n * SSTR + kk + tg * 2);
                bf[nt][1] = ld32h(b_s + n * SSTR + kk + tg * 2 + 8);
            }
#pragma unroll
            for (int mt = 0; mt < 4; mt++)
#pragma unroll
                for (int nt = 0; nt < 4; nt++) mma16816(acc[mt][nt], af[mt], bf[nt]);
        }
    }

#pragma unroll
    for (int mt = 0; mt < 4; mt++) {
        int row0 = bm + wm + mt * 16 + g;
#pragma unroll
        for (int nt = 0; nt < 4; nt++) {
            int col = bn + wn + nt * 8 + tg * 2;
            float b0 = bias[col], b1 = bias[col + 1];
            float2 v0 = make_float2(acc[mt][nt][0] + b0, acc[mt][nt][1] + b1);
            float2 v1 = make_float2(acc[mt][nt][2] + b0, acc[mt][nt][3] + b1);
            *reinterpret_cast<float2*>(&C[(long)row0 * N + col])       = v0;
            *reinterpret_cast<float2*>(&C[(long)(row0 + 8) * N + col]) = v1;
        }
    }
}

// ---------------- persistent GRU recurrence ----------------
// GROUPS batch-groups of ROWS rows; CJ = H/16 column-CTAs per group, own barrier.
// 8 warps = KSPLIT K-chunks x (ROWS/16) M-halves. Warp self-stages its 16 rows x
// K-chunk in TWO K-half commit groups: MMA on half 0 overlaps half 1's arrival.
template <int H, int LAYER, int ROWS, int KSPLIT, int GROUPS>
__global__ __launch_bounds__(256) void rec_kernel(
        const float* __restrict__ gx, const __half* __restrict__ whh,
        const float* __restrict__ bhh, float* __restrict__ outp,
        unsigned int* __restrict__ barctr) {
    constexpr int K = H;
    constexpr int Kw = K / KSPLIT;
    constexpr int KI = Kw / 16;
    constexpr int CJ = H / 16;
    constexpr int GA = 3 * H;
    constexpr int STRIDE = H + 8;
    constexpr int VAL = (ROWS * 16) / 256;

    extern __shared__ unsigned char smem[];
    __half*   sH   = reinterpret_cast<__half*>(smem);                                // [ROWS][STRIDE]
    uint32_t* sB   = reinterpret_cast<uint32_t*>(smem + (size_t)ROWS * STRIDE * 2);  // [KSPLIT*KI*6][32][2]
    float*    sRed = reinterpret_cast<float*>(smem + (size_t)ROWS * STRIDE * 2 + (size_t)KSPLIT * KI * 6 * 64 * 4); // [KSPLIT][ROWS][48]

    const int tid = threadIdx.x;
    const int w = tid >> 5, lane = tid & 31;
    const int km = w % KSPLIT, mh = w / KSPLIT;
    const int g = lane >> 2, tg = lane & 3;
    const int grp = blockIdx.x % GROUPS;
    const int j0 = (blockIdx.x / GROUPS) * 16;
    const int row0 = grp * ROWS;
    const int mrow = mh * 16;
    const int lr = lane & 15, lc = (lane >> 4) << 3;
    unsigned int* ctr = barctr + grp;

    // Stage W_hh fragments once: 48 gate cols = 6 n-tiles of 8.
    if (mh == 0) {
#pragma unroll
        for (int i = 0; i < KI; i++) {
            int k0 = km * Kw + i * 16;
#pragma unroll
            for (int nt = 0; nt < 6; nt++) {
                int gate = nt >> 1;
                int jl = (nt & 1) * 8 + g;
                int n = gate * H + j0 + jl;
                const __half* p = whh + (long)n * K + k0 + tg * 2;
                int base2 = ((((km * KI + i) * 6 + nt) * 32) + lane) * 2;
                sB[base2]     = ld32h(p);
                sB[base2 + 1] = ld32h(p + 8);
            }
        }
    }

    // Per-thread gate state.
    float hp[VAL];
    float br[VAL], bz[VAL], bn_[VAL];
    int   bloc[VAL], jidx[VAL];
    const float* gxbase[VAL];
#pragma unroll
    for (int v = 0; v < VAL; v++) {
        int idx = tid + v * 256;
        int b = idx >> 4, jl = idx & 15, j = j0 + jl;
        hp[v] = 0.0f;
        bloc[v] = b; jidx[v] = j;
        br[v]  = bhh[j];
        bz[v]  = bhh[H + j];
        bn_[v] = bhh[2 * H + j];
        gxbase[v] = gx + (long)(row0 + b) * TT * GA + j;
        d_hbuf16[0][(row0 + b) * H + j] = __float2half(0.0f);
    }

    // Prefetch gx for t=0.
    float xr[VAL], xz[VAL], xn[VAL];
#pragma unroll
    for (int v = 0; v < VAL; v++) {
        const float* p = gxbase[v];
        xr[v] = __ldg(p);
        xz[v] = __ldg(p + H);
        xn[v] = __ldg(p + 2 * H);
    }

    unsigned int ibar = 0;
    gridbar(ctr, (++ibar) * CJ);

    // 16B chunks per K-half per lane-iteration mapping:
    constexpr int HALFW = Kw / 2;                 // halfs per K-half
    constexpr int CPR = HALFW / 8;                // 16B chunks per row per half
    constexpr int ITER = (16 * CPR) / 32;         // lane iterations per half

    for (int t = 0; t < TT; t++) {
        const int cur = t & 1, nxt = cur ^ 1;
        const __half* hA = d_hbuf16[cur] + (long)row0 * H;

        // Self-stage in two K-half groups.
#pragma unroll
        for (int hf = 0; hf < 2; hf++) {
            int colbase = km * Kw + hf * HALFW;
#pragma unroll
            for (int c = 0; c < ITER; c++) {
                int idx = c * 32 + lane;
                int r = idx / CPR, cc = idx % CPR;
                int row = mrow + r, col = colbase + cc * 8;
                cp16(&sH[row * STRIDE + col], hA + (long)row * H + col);
            }
            cp_commit();
        }

        float acc[6][4];
#pragma unroll
        for (int q = 0; q < 6; q++)
#pragma unroll
            for (int e = 0; e < 4; e++) acc[q][e] = 0.0f;

        // First K-half: wait only group 0 (1 group still outstanding).
        cp_wait1();
        __syncwarp(0xffffffffu);
#pragma unroll
        for (int i = 0; i < KI / 2; i++) {
            int k0 = km * Kw + i * 16;
            uint32_t a[4];
            ldsm_x4(a, sH + (mrow + lr) * STRIDE + k0 + lc);
#pragma unroll
            for (int nt = 0; nt < 6; nt++) {
                int base2 = ((((km * KI + i) * 6 + nt) * 32) + lane) * 2;
                uint2 bp = *reinterpret_cast<const uint2*>(&sB[base2]);
                uint32_t b[2] = { bp.x, bp.y };
                mma16816(acc[nt], a, b);
            }
        }
        // Second K-half.
        cp_wait0();
        __syncwarp(0xffffffffu);
#pragma unroll
        for (int i = KI / 2; i < KI; i++) {
            int k0 = km * Kw + i * 16;
            uint32_t a[4];
            ldsm_x4(a, sH + (mrow + lr) * STRIDE + k0 + lc);
#pragma unroll
            for (int nt = 0; nt < 6; nt++) {
                int base2 = ((((km * KI + i) * 6 + nt) * 32) + lane) * 2;
                uint2 bp = *reinterpret_cast<const uint2*>(&sB[base2]);
                uint32_t b[2] = { bp.x, bp.y };
                mma16816(acc[nt], a, b);
            }
        }

        // per-K-chunk partials -> SMEM: [KSPLIT][ROWS][48]
#pragma unroll
        for (int nt = 0; nt < 6; nt++) {
            float* c = acc[nt];
            int col = nt * 8 + tg * 2;
            int row = mrow + g;
            *reinterpret_cast<float2*>(&sRed[(km * ROWS + row) * 48 + col])     = make_float2(c[0], c[1]);
            *reinterpret_cast<float2*>(&sRed[(km * ROWS + row + 8) * 48 + col]) = make_float2(c[2], c[3]);
        }
        __syncthreads();

        // gate math.
#pragma unroll
        for (int v = 0; v < VAL; v++) {
            int b = bloc[v], j = jidx[v];
            int jl = j - j0;
            float hr = br[v], hz = bz[v], hn = bn_[v];
#pragma unroll
            for (int kk = 0; kk < KSPLIT; kk++) {
                const float* rr = &sRed[(kk * ROWS + b) * 48];
                hr += rr[jl];
                hz += rr[16 + jl];
                hn += rr[32 + jl];
            }
            float r = sigm(xr[v] + hr);
            float z = sigm(xz[v] + hz);
            float n = tanh_fast(fmaf(r, hn, xn[v]));
            float hnew = fmaf(z, hp[v] - n, n);
            hp[v] = hnew;
            d_hbuf16[nxt][(row0 + b) * H + j] = __float2half(hnew);
            if (LAYER == 1) {
                d_h1seq[((long)(row0 + b) * TT + t) * H + j] = __float2half(fmaxf(hnew, 0.0f));
            } else {
                outp[((long)(row0 + b) * TT + t) * H + j] = hnew;
            }
        }

        // Prefetch gx for t+1 BEFORE the barrier.
        if (t + 1 < TT) {
#pragma unroll
            for (int v = 0; v < VAL; v++) {
                const float* p = gxbase[v] + (long)(t + 1) * GA;
                xr[v] = __ldg(p);
                xz[v] = __ldg(p + H);
                xn[v] = __ldg(p + 2 * H);
            }
        }
        gridbar(ctr, (++ibar) * CJ);
    }
}

// ---------------- launch ----------------
extern "C" void kernel_launch(void* const* d_in, const int* in_sizes, int n_in,
                              void* d_out, int out_size) {
    const float* x    = (const float*)d_in[0];
    const float* wih1 = (const float*)d_in[1];
    const float* whh1 = (const float*)d_in[2];
    const float* bih1 = (const float*)d_in[3];
    const float* bhh1 = (const float*)d_in[4];
    const float* wih2 = (const float*)d_in[5];
    const float* whh2 = (const float*)d_in[6];
    const float* bih2 = (const float*)d_in[7];
    const float* bhh2 = (const float*)d_in[8];
    float* out = (float*)d_out;

    void *p_xh, *p_wih1, *p_whh1, *p_wih2, *p_whh2, *p_gx1, *p_gx2, *p_h1, *p_bar1, *p_bar2;
    cudaGetSymbolAddress(&p_xh, d_xh);
    cudaGetSymbolAddress(&p_wih1, d_wih1);
    cudaGetSymbolAddress(&p_whh1, d_whh1);
    cudaGetSymbolAddress(&p_wih2, d_wih2);
    cudaGetSymbolAddress(&p_whh2, d_whh2);
    cudaGetSymbolAddress(&p_gx1, d_gx1);
    cudaGetSymbolAddress(&p_gx2, d_gx2);
    cudaGetSymbolAddress(&p_h1, d_h1seq);
    cudaGetSymbolAddress(&p_bar1, d_bar1);
    cudaGetSymbolAddress(&p_bar2, d_bar2);

    const int GEMM_SMEM = GSTG * 128 * SSTR * 2 * 2;   // 61440
    cudaFuncSetAttribute(gemm_tn_kernel, cudaFuncAttributeMaxDynamicSharedMemorySize, GEMM_SMEM);

    const int SMEM1 = 16 * (512 + 8) * 2 + 8 * 4 * 6 * 64 * 4 + 8 * 16 * 48 * 4;    // 90368
    const int SMEM2 = 32 * (1024 + 8) * 2 + 4 * 16 * 6 * 64 * 4 + 4 * 32 * 48 * 4;  // 188928
    cudaFuncSetAttribute((const void*)rec_kernel<512, 1, 16, 8, 4>,
                         cudaFuncAttributeMaxDynamicSharedMemorySize, SMEM1);
    cudaFuncSetAttribute((const void*)rec_kernel<1024, 2, 32, 4, 2>,
                         cudaFuncAttributeMaxDynamicSharedMemorySize, SMEM2);

    prep_kernel<<<2048, 256>>>(x, wih1, whh1, wih2, whh2);

    {   // gx1 = x @ W_ih1^T + b_ih1 : [16384,1536], K=1024
        dim3 grid(1536 / 128, 16384 / 128);
        gemm_tn_kernel<<<grid, 256, GEMM_SMEM>>>((const __half*)p_xh, (const __half*)p_wih1,
                                                 bih1, (float*)p_gx1, 16384, 1536, 1024);
    }

    rec_kernel<512, 1, 16, 8, 4><<<128, 256, SMEM1>>>(
        (const float*)p_gx1, (const __half*)p_whh1, bhh1, nullptr, (unsigned int*)p_bar1);

    {   // gx2 = relu(h1) @ W_ih2^T + b_ih2 : [16384,3072], K=512
        dim3 grid(3072 / 128, 16384 / 128);
        gemm_tn_kernel<<<grid, 256, GEMM_SMEM>>>((const __half*)p_h1, (const __half*)p_wih2,
                                                 bih2, (float*)p_gx2, 16384, 3072, 512);
    }

    rec_kernel<1024, 2, 32, 4, 2><<<128, 256, SMEM2>>>(
        (const float*)p_gx2, (const __half*)p_whh2, bhh2, out, (unsigned int*)p_bar2);
}